// round 5
// baseline (speedup 1.0000x reference)
#include <cuda_runtime.h>
#include <math.h>

typedef unsigned long long ull;

// Problem constants
#define BATCH  4
#define SEQ    1024
#define CDIM   1024
#define HEADS  16
#define DHEAD  64
#define CHUNK  64
#define NCHUNK 16
#define TOPKN  32
#define SCALEF 0.125f   // 1/sqrt(64)

// Scratch (allocation-free rule: device globals)
__device__ float g_q[BATCH*SEQ*CDIM];
__device__ float g_k[BATCH*SEQ*CDIM];
__device__ float g_v[BATCH*SEQ*CDIM];
__device__ float g_attn[BATCH*SEQ*CDIM];

// ---------------- f32x2 packed helpers (Blackwell FFMA2 path) --------------
__device__ __forceinline__ ull pack2(float lo, float hi) {
    ull r; asm("mov.b64 %0, {%1, %2};" : "=l"(r) : "f"(lo), "f"(hi)); return r;
}
__device__ __forceinline__ float lo2(ull v) {
    float a, b; asm("mov.b64 {%0, %1}, %2;" : "=f"(a), "=f"(b) : "l"(v)); return a;
}
__device__ __forceinline__ float hi2(ull v) {
    float a, b; asm("mov.b64 {%0, %1}, %2;" : "=f"(a), "=f"(b) : "l"(v)); return b;
}
__device__ __forceinline__ ull ffma2(ull a, ull b, ull c) {
    ull d; asm("fma.rn.f32x2 %0, %1, %2, %3;" : "=l"(d) : "l"(a), "l"(b), "l"(c));
    return d;
}

// ---------------------------------------------------------------------------
// Tiled FP32 GEMM, f32x2 FMA. C[M,N] = A[M,K] @ B[K,N], row-major.
// BM=128, BN=64, BK=16, 256 threads, 8x4 per thread (row-pairs packed f32x2).
// blockIdx.z selects (B,C) pair -> one launch covers the Q/K/V GEMMs.
// ---------------------------------------------------------------------------
#define GBM 128
#define GBN 64
#define GBK 16

__global__ __launch_bounds__(256)
void sgemm3_kernel(const float* __restrict__ A,
                   const float* __restrict__ B0, const float* __restrict__ B1,
                   const float* __restrict__ B2,
                   float* __restrict__ C0, float* __restrict__ C1,
                   float* __restrict__ C2,
                   int M, int N, int K)
{
    const int z = blockIdx.z;
    const float* B = (z == 0) ? B0 : ((z == 1) ? B1 : B2);
    float*       C = (z == 0) ? C0 : ((z == 1) ? C1 : C2);

    __shared__ float As[GBK][GBM];   // transposed A tile (8 KB)
    __shared__ float Bs[GBK][GBN];   // 4 KB

    const int tid = threadIdx.x;
    const int bx = blockIdx.x, by = blockIdx.y;

    const int a_r = tid >> 1;            // 0..127
    const int a_c = (tid & 1) * 8;       // 0 or 8
    const int b_r = tid >> 4;            // 0..15
    const int b_c = (tid & 15) * 4;      // 0..60

    const float* Ab = A + (size_t)(by * GBM) * K;
    const float* Bb = B + bx * GBN;

    const int tx = tid & 15;             // col group: 4 cols
    const int ty = tid >> 4;             // row group: 8 rows

    ull acc2[4][4];                      // row-pair x col, packed f32x2
#pragma unroll
    for (int i = 0; i < 4; i++)
#pragma unroll
        for (int j = 0; j < 4; j++) acc2[i][j] = 0ull;

    for (int k0 = 0; k0 < K; k0 += GBK) {
        float4 av0 = *(const float4*)(Ab + (size_t)a_r * K + k0 + a_c);
        float4 av1 = *(const float4*)(Ab + (size_t)a_r * K + k0 + a_c + 4);
        As[a_c + 0][a_r] = av0.x; As[a_c + 1][a_r] = av0.y;
        As[a_c + 2][a_r] = av0.z; As[a_c + 3][a_r] = av0.w;
        As[a_c + 4][a_r] = av1.x; As[a_c + 5][a_r] = av1.y;
        As[a_c + 6][a_r] = av1.z; As[a_c + 7][a_r] = av1.w;
        *(float4*)&Bs[b_r][b_c] = *(const float4*)(Bb + (size_t)(k0 + b_r) * N + b_c);
        __syncthreads();

#pragma unroll
        for (int kk = 0; kk < GBK; kk++) {
            ull ar2[4];
#pragma unroll
            for (int ip = 0; ip < 4; ip++)
                ar2[ip] = *(const ull*)&As[kk][ty * 8 + 2 * ip];
            float4 bv = *(const float4*)&Bs[kk][tx * 4];
            float br[4] = { bv.x, bv.y, bv.z, bv.w };
#pragma unroll
            for (int j = 0; j < 4; j++) {
                ull bd = pack2(br[j], br[j]);
#pragma unroll
                for (int ip = 0; ip < 4; ip++)
                    acc2[ip][j] = ffma2(ar2[ip], bd, acc2[ip][j]);
            }
        }
        __syncthreads();
    }

#pragma unroll
    for (int ip = 0; ip < 4; ip++) {
        float r0[4], r1[4];
#pragma unroll
        for (int j = 0; j < 4; j++) { r0[j] = lo2(acc2[ip][j]); r1[j] = hi2(acc2[ip][j]); }
        float* c0 = C + (size_t)(by * GBM + ty * 8 + 2 * ip) * N + bx * GBN + tx * 4;
        float* c1 = c0 + N;
        *(float4*)c0 = make_float4(r0[0], r0[1], r0[2], r0[3]);
        *(float4*)c1 = make_float4(r1[0], r1[1], r1[2], r1[3]);
    }
}

// ---------------------------------------------------------------------------
// Sparse chunked attention.
// Grid: (SEQ/32, HEADS, BATCH); 256 threads (8 warps); warp handles 4 queries.
// Per chunk: scores via packed f32x2 (keys lane & lane+32 per lane), exact
// 32nd-largest via two-array bitonic split (sort {hi} asc + {lo} desc, D=max,
// thr=min(D)), zero below thr, softmax over all 64 (zeros included).
// PV: p staged in smem (LDS128 broadcast), v read by coalesced LDG (L2-hot).
// ---------------------------------------------------------------------------
#define QB 32

__device__ __forceinline__ void bcas(float& x, int i, int j, int k, bool desc) {
    float pv = __shfl_xor_sync(0xffffffffu, x, j);
    bool keep_min = (((i & j) == 0) == ((((i & k) == 0) ? 1 : 0) ^ (desc ? 1 : 0)));
    x = keep_min ? fminf(x, pv) : fmaxf(x, pv);
}

__global__ __launch_bounds__(256)
void attn_kernel(const float* __restrict__ q, const float* __restrict__ k,
                 const float* __restrict__ v, const float* __restrict__ imp,
                 const float* __restrict__ temps, float* __restrict__ out)
{
    __shared__ float q_sT[DHEAD][QB];          // [d][query]   8 KB
    __shared__ ull   kT2[DHEAD][CHUNK/2 + 1];  // key pairs (j, j+32)  16.9 KB
    __shared__ float p_s[8][CHUNK][4];         // [warp][key][query]   8 KB
    __shared__ float fac_s[QB];

    const int b  = blockIdx.z;
    const int h  = blockIdx.y;
    const int t0 = blockIdx.x * QB;
    const int tid  = threadIdx.x;
    const int lane = tid & 31;
    const int wid  = tid >> 5;

    // per-query factor: SCALE / clip(temp) * sigmoid((sigmoid(imp)-0.5)*10)
    if (tid < QB) {
        float tmp = temps[b * HEADS + h];
        tmp = fminf(fmaxf(tmp, 0.1f), 100.f);
        float is = imp[((size_t)b * SEQ + (t0 + tid)) * HEADS + h];
        float ip = 1.f / (1.f + expf(-is));
        float mw = 1.f / (1.f + expf(-((ip - 0.5f) * 10.f)));
        fac_s[tid] = (SCALEF / tmp) * mw;
    }

    // load 32 queries (transposed)
    for (int i = tid; i < QB * DHEAD / 4; i += 256) {
        int qq = i / (DHEAD / 4);
        int dd = (i % (DHEAD / 4)) * 4;
        float4 qv = *(const float4*)&q[((size_t)b * SEQ + (t0 + qq)) * CDIM + h * DHEAD + dd];
        q_sT[dd + 0][qq] = qv.x;
        q_sT[dd + 1][qq] = qv.y;
        q_sT[dd + 2][qq] = qv.z;
        q_sT[dd + 3][qq] = qv.w;
    }

    ull acc2[4] = {0ull, 0ull, 0ull, 0ull};    // per query, dims (d0, d0+1)
    const int d0 = lane * 2;
    const int qbase = wid * 4;

    for (int ck = 0; ck < NCHUNK; ck++) {
        __syncthreads();   // protects q_sT/fac_s first iter, kT2 reuse after
        const int kt0 = ck * CHUNK;
        // stage K transposed into pair layout
        for (int i = tid; i < CHUNK * DHEAD / 4; i += 256) {
            int j  = i / (DHEAD / 4);
            int dd = (i % (DHEAD / 4)) * 4;
            float4 kv = *(const float4*)&k[((size_t)b * SEQ + (kt0 + j)) * CDIM + h * DHEAD + dd];
            const int slot = j & 31, half = j >> 5;
            ((float*)&kT2[dd + 0][slot])[half] = kv.x;
            ((float*)&kT2[dd + 1][slot])[half] = kv.y;
            ((float*)&kT2[dd + 2][slot])[half] = kv.z;
            ((float*)&kT2[dd + 3][slot])[half] = kv.w;
        }
        __syncthreads();

        // scores: lane owns keys (lane, lane+32); queries packed in f32x2
        ull s0_01 = 0, s0_23 = 0, s1_01 = 0, s1_23 = 0;
#pragma unroll 8
        for (int d = 0; d < DHEAD; d++) {
            ull kp = kT2[d][lane];
            float4 qv = *(const float4*)&q_sT[d][qbase];
            ull q01 = pack2(qv.x, qv.y);
            ull q23 = pack2(qv.z, qv.w);
            float k0v = lo2(kp), k1v = hi2(kp);
            ull k0d = pack2(k0v, k0v), k1d = pack2(k1v, k1v);
            s0_01 = ffma2(q01, k0d, s0_01);
            s0_23 = ffma2(q23, k0d, s0_23);
            s1_01 = ffma2(q01, k1d, s1_01);
            s1_23 = ffma2(q23, k1d, s1_23);
        }

        float s0[4] = { lo2(s0_01), hi2(s0_01), lo2(s0_23), hi2(s0_23) };
        float s1[4] = { lo2(s1_01), hi2(s1_01), lo2(s1_23), hi2(s1_23) };

#pragma unroll
        for (int qi = 0; qi < 4; qi++) {
            float f  = fac_s[qbase + qi];
            float a0 = s0[qi] * f;
            float a1 = s1[qi] * f;

            // exact 32nd-largest of 64:
            // per-lane (lo,hi); sort {hi} ascending, {lo} descending across
            // lanes; D = pointwise max = top-32 multiset; thr = min(D).
            float hv = fmaxf(a0, a1);
            float lv = fminf(a0, a1);
#pragma unroll
            for (int kk = 2; kk <= 32; kk <<= 1) {
#pragma unroll
                for (int j = kk >> 1; j > 0; j >>= 1) {
                    bcas(hv, lane, j, kk, false);
                    bcas(lv, lane, j, kk, true);
                }
            }
            float D = fmaxf(hv, lv);
            float thr = D;
#pragma unroll
            for (int o = 16; o; o >>= 1)
                thr = fminf(thr, __shfl_xor_sync(0xffffffffu, thr, o));

            float m0 = (a0 >= thr) ? a0 : 0.f;
            float m1 = (a1 >= thr) ? a1 : 0.f;
            float mx = fmaxf(m0, m1);
#pragma unroll
            for (int o = 16; o; o >>= 1)
                mx = fmaxf(mx, __shfl_xor_sync(0xffffffffu, mx, o));
            float e0 = __expf(m0 - mx);
            float e1 = __expf(m1 - mx);
            float ds = e0 + e1;
#pragma unroll
            for (int o = 16; o; o >>= 1)
                ds += __shfl_xor_sync(0xffffffffu, ds, o);
            float inv = 1.f / ds;
            p_s[wid][lane][qi]      = e0 * inv;
            p_s[wid][lane + 32][qi] = e1 * inv;
        }
        __syncwarp();

        // PV: p from smem (LDS128 broadcast), v via coalesced LDG (L2/L1-hot)
        const float* vrow = &v[((size_t)b * SEQ + kt0) * CDIM + h * DHEAD + d0];
#pragma unroll 8
        for (int j = 0; j < CHUNK; j++) {
            float4 pj = *(const float4*)&p_s[wid][j][0];
            float2 vv = *(const float2*)(vrow + (size_t)j * CDIM);
            ull v2 = pack2(vv.x, vv.y);
            acc2[0] = ffma2(pack2(pj.x, pj.x), v2, acc2[0]);
            acc2[1] = ffma2(pack2(pj.y, pj.y), v2, acc2[1]);
            acc2[2] = ffma2(pack2(pj.z, pj.z), v2, acc2[2]);
            acc2[3] = ffma2(pack2(pj.w, pj.w), v2, acc2[3]);
        }
    }

    // write [B,T,C]; normalizer sum(p) == NCHUNK == 16 exactly
    const float invn = 1.f / 16.f;
#pragma unroll
    for (int qi = 0; qi < 4; qi++) {
        int ql = qbase + qi;
        float2 o2 = make_float2(lo2(acc2[qi]) * invn, hi2(acc2[qi]) * invn);
        *(float2*)&out[((size_t)b * SEQ + (t0 + ql)) * CDIM + h * DHEAD + d0] = o2;
    }
}

// ---------------------------------------------------------------------------
// Launch
// ---------------------------------------------------------------------------
extern "C" void kernel_launch(void* const* d_in, const int* in_sizes, int n_in,
                              void* d_out, int out_size)
{
    const float* x    = (const float*)d_in[0];
    const float* impS = (const float*)d_in[1];
    const float* temp = (const float*)d_in[2];
    const float* Wq   = (const float*)d_in[3];
    const float* Wk   = (const float*)d_in[4];
    const float* Wv   = (const float*)d_in[5];
    const float* Wo   = (const float*)d_in[6];
    float* outp = (float*)d_out;

    float *pq, *pk, *pv, *pa;
    cudaGetSymbolAddress((void**)&pq, g_q);
    cudaGetSymbolAddress((void**)&pk, g_k);
    cudaGetSymbolAddress((void**)&pv, g_v);
    cudaGetSymbolAddress((void**)&pa, g_attn);

    const int M = BATCH * SEQ;   // 4096
    const int N = CDIM;          // 1024
    const int K = CDIM;          // 1024

    // fused QKV projection (grid.z selects weight/output)
    dim3 g3(N / GBN, M / GBM, 3);
    sgemm3_kernel<<<g3, 256>>>(x, Wq, Wk, Wv, pq, pk, pv, M, N, K);

    dim3 agrid(SEQ / QB, HEADS, BATCH);
    attn_kernel<<<agrid, 256>>>(pq, pk, pv, impS, temp, pa);

    dim3 g1(N / GBN, M / GBM, 1);
    sgemm3_kernel<<<g1, 256>>>(pa, Wo, Wo, Wo, outp, outp, outp, M, N, K);
}

// round 7
// speedup vs baseline: 1.7772x; 1.7772x over previous
#include <cuda_runtime.h>
#include <math.h>
#include <stdint.h>

typedef unsigned long long ull;

// Problem constants
#define BATCH  4
#define SEQ    1024
#define CDIM   1024
#define HEADS  16
#define DHEAD  64
#define CHUNK  64
#define NCHUNK 16
#define TOPKN  32
#define SCALEF 0.125f   // 1/sqrt(64)

// Scratch (allocation-free rule: device globals)
__device__ float g_q[BATCH*SEQ*CDIM];
__device__ float g_k[BATCH*SEQ*CDIM];
__device__ float g_v[BATCH*SEQ*CDIM];
__device__ float g_attn[BATCH*SEQ*CDIM];

// ---------------- f32x2 packed helpers (Blackwell FFMA2 path) --------------
__device__ __forceinline__ ull pack2(float lo, float hi) {
    ull r; asm("mov.b64 %0, {%1, %2};" : "=l"(r) : "f"(lo), "f"(hi)); return r;
}
__device__ __forceinline__ float lo2(ull v) {
    float a, b; asm("mov.b64 {%0, %1}, %2;" : "=f"(a), "=f"(b) : "l"(v)); return a;
}
__device__ __forceinline__ float hi2(ull v) {
    float a, b; asm("mov.b64 {%0, %1}, %2;" : "=f"(a), "=f"(b) : "l"(v)); return b;
}
__device__ __forceinline__ ull ffma2(ull a, ull b, ull c) {
    ull d; asm("fma.rn.f32x2 %0, %1, %2, %3;" : "=l"(d) : "l"(a), "l"(b), "l"(c));
    return d;
}

// ---------------------------------------------------------------------------
// TF32 tensor-core GEMM: C[M,N] = A[M,K] @ B[K,N], row-major fp32 in/out.
// BM=BN=128, BK=16, 256 threads = 8 warps in 2(m)x4(n) grid; warp tile 64x32.
// Each warp: 4x4 mma.sync.m16n8k8.tf32 tiles per k8-step, fp32 accumulators.
// blockIdx.z selects (B,C) pair -> one launch covers the Q/K/V GEMMs.
// ---------------------------------------------------------------------------
#define TBM 128
#define TBN 128
#define TBK 16
#define TPAD 4

__device__ __forceinline__ uint32_t f2tf(float f) {
    uint32_t u; asm("cvt.rna.tf32.f32 %0, %1;" : "=r"(u) : "f"(f)); return u;
}

__device__ __forceinline__ void mma_tf32(float c[4], uint32_t a0, uint32_t a1,
                                         uint32_t a2, uint32_t a3,
                                         uint32_t b0, uint32_t b1) {
    asm volatile(
        "mma.sync.aligned.m16n8k8.row.col.f32.tf32.tf32.f32 "
        "{%0,%1,%2,%3}, {%4,%5,%6,%7}, {%8,%9}, {%0,%1,%2,%3};"
        : "+f"(c[0]), "+f"(c[1]), "+f"(c[2]), "+f"(c[3])
        : "r"(a0), "r"(a1), "r"(a2), "r"(a3), "r"(b0), "r"(b1));
}

__global__ __launch_bounds__(256)
void tf32gemm_kernel(const float* __restrict__ A,
                     const float* __restrict__ B0, const float* __restrict__ B1,
                     const float* __restrict__ B2,
                     float* __restrict__ C0, float* __restrict__ C1,
                     float* __restrict__ C2,
                     int M, int N, int K)
{
    const int z = blockIdx.z;
    const float* B = (z == 0) ? B0 : ((z == 1) ? B1 : B2);
    float*       C = (z == 0) ? C0 : ((z == 1) ? C1 : C2);

    __shared__ uint32_t As[TBK][TBM + TPAD];   // [k][m], tf32 bits (8.4 KB)
    __shared__ uint32_t Bs[TBK][TBN + TPAD];   // [k][n], tf32 bits (8.4 KB)

    const int tid  = threadIdx.x;
    const int lane = tid & 31;
    const int wid  = tid >> 5;
    const int bx = blockIdx.x, by = blockIdx.y;

    const int g = lane >> 2;       // group id (0..7)
    const int t = lane & 3;        // thread-in-group (0..3)
    const int wm = (wid & 1) * 64; // warp m offset
    const int wn = (wid >> 1) * 32;// warp n offset

    const int a_r = tid >> 1;            // 0..127
    const int a_c = (tid & 1) * 8;       // 0 or 8
    const int b_r = tid >> 4;            // 0..15
    const int b_c = (tid & 15) * 8;      // 0..120

    const float* Ab = A + (size_t)(by * TBM) * K;
    const float* Bb = B + bx * TBN;

    float c[4][4][4];
#pragma unroll
    for (int i = 0; i < 4; i++)
#pragma unroll
        for (int j = 0; j < 4; j++)
#pragma unroll
            for (int e = 0; e < 4; e++) c[i][j][e] = 0.f;

    for (int k0 = 0; k0 < K; k0 += TBK) {
        // stage A (transposed) and B, converting fp32 -> tf32 (rna)
        float4 av0 = *(const float4*)(Ab + (size_t)a_r * K + k0 + a_c);
        float4 av1 = *(const float4*)(Ab + (size_t)a_r * K + k0 + a_c + 4);
        As[a_c + 0][a_r] = f2tf(av0.x); As[a_c + 1][a_r] = f2tf(av0.y);
        As[a_c + 2][a_r] = f2tf(av0.z); As[a_c + 3][a_r] = f2tf(av0.w);
        As[a_c + 4][a_r] = f2tf(av1.x); As[a_c + 5][a_r] = f2tf(av1.y);
        As[a_c + 6][a_r] = f2tf(av1.z); As[a_c + 7][a_r] = f2tf(av1.w);

        float4 bv0 = *(const float4*)(Bb + (size_t)(k0 + b_r) * N + b_c);
        float4 bv1 = *(const float4*)(Bb + (size_t)(k0 + b_r) * N + b_c + 4);
        Bs[b_r][b_c + 0] = f2tf(bv0.x); Bs[b_r][b_c + 1] = f2tf(bv0.y);
        Bs[b_r][b_c + 2] = f2tf(bv0.z); Bs[b_r][b_c + 3] = f2tf(bv0.w);
        Bs[b_r][b_c + 4] = f2tf(bv1.x); Bs[b_r][b_c + 5] = f2tf(bv1.y);
        Bs[b_r][b_c + 6] = f2tf(bv1.z); Bs[b_r][b_c + 7] = f2tf(bv1.w);
        __syncthreads();

#pragma unroll
        for (int s = 0; s < 2; s++) {
            const int kA = s * 8 + t;
            uint32_t af[4][4];
#pragma unroll
            for (int i = 0; i < 4; i++) {
                const int mb = wm + i * 16 + g;
                af[i][0] = As[kA][mb];
                af[i][1] = As[kA][mb + 8];
                af[i][2] = As[kA + 4][mb];
                af[i][3] = As[kA + 4][mb + 8];
            }
            uint32_t bf[4][2];
#pragma unroll
            for (int j = 0; j < 4; j++) {
                const int nb = wn + j * 8 + g;
                bf[j][0] = Bs[kA][nb];
                bf[j][1] = Bs[kA + 4][nb];
            }
#pragma unroll
            for (int i = 0; i < 4; i++)
#pragma unroll
                for (int j = 0; j < 4; j++)
                    mma_tf32(c[i][j], af[i][0], af[i][1], af[i][2], af[i][3],
                             bf[j][0], bf[j][1]);
        }
        __syncthreads();
    }

    // epilogue: each thread owns (rows g, g+8) x (cols 2t, 2t+1) per tile
#pragma unroll
    for (int i = 0; i < 4; i++) {
        const int row = by * TBM + wm + i * 16 + g;
#pragma unroll
        for (int j = 0; j < 4; j++) {
            const int col = bx * TBN + wn + j * 8 + 2 * t;
            *(float2*)&C[(size_t)row * N + col]       = make_float2(c[i][j][0], c[i][j][1]);
            *(float2*)&C[(size_t)(row + 8) * N + col] = make_float2(c[i][j][2], c[i][j][3]);
        }
    }
}

// ---------------------------------------------------------------------------
// Sparse chunked attention (round-4 structure: smem K/V tiles, shfl PV).
// Grid: (SEQ/32, HEADS, BATCH); 256 threads (8 warps); warp handles 4 queries.
// Exact 32nd-largest via two-array bitonic split: sort {max-pair} ascending and
// {min-pair} descending across lanes, D = pointwise max = top-32 multiset,
// thr = min(D). Zero below thr, softmax over all 64 (zeros included), p@v.
// ---------------------------------------------------------------------------
#define QB 32

__device__ __forceinline__ void bcas(float& x, int i, int j, int k, bool desc) {
    float pv = __shfl_xor_sync(0xffffffffu, x, j);
    bool keep_min = (((i & j) == 0) == ((((i & k) == 0) ? 1 : 0) ^ (desc ? 1 : 0)));
    x = keep_min ? fminf(x, pv) : fmaxf(x, pv);
}

__global__ __launch_bounds__(256)
void attn_kernel(const float* __restrict__ q, const float* __restrict__ k,
                 const float* __restrict__ v, const float* __restrict__ imp,
                 const float* __restrict__ temps, float* __restrict__ out)
{
    __shared__ float q_sT[DHEAD][QB];          // transposed queries, 8 KB
    __shared__ ull   kT2[DHEAD][CHUNK / 2];    // key pairs (j, j+32), 16 KB
    __shared__ float v_s[CHUNK][DHEAD];        // 16 KB
    __shared__ float fac_s[QB];

    const int b  = blockIdx.z;
    const int h  = blockIdx.y;
    const int t0 = blockIdx.x * QB;
    const int tid  = threadIdx.x;
    const int lane = tid & 31;
    const int wid  = tid >> 5;

    // per-query score factor: SCALE / clip(temp) * sigmoid((sigmoid(imp)-0.5)*10)
    if (tid < QB) {
        float tmp = temps[b * HEADS + h];
        tmp = fminf(fmaxf(tmp, 0.1f), 100.f);
        float is = imp[((size_t)b * SEQ + (t0 + tid)) * HEADS + h];
        float ip = 1.f / (1.f + expf(-is));
        float mw = 1.f / (1.f + expf(-((ip - 0.5f) * 10.f)));
        fac_s[tid] = (SCALEF / tmp) * mw;
    }

    // load 32 queries (transposed: q_sT[d][query])
    for (int i = tid; i < QB * DHEAD / 4; i += 256) {
        int qq = i / (DHEAD / 4);
        int dd = (i % (DHEAD / 4)) * 4;
        float4 qv = *(const float4*)&q[((size_t)b * SEQ + (t0 + qq)) * CDIM + h * DHEAD + dd];
        q_sT[dd + 0][qq] = qv.x;
        q_sT[dd + 1][qq] = qv.y;
        q_sT[dd + 2][qq] = qv.z;
        q_sT[dd + 3][qq] = qv.w;
    }

    ull acc01x = 0, acc01y = 0, acc23x = 0, acc23y = 0;  // (q-pair) x (dim)
    const int d0 = lane * 2;
    const int qbase = wid * 4;

    for (int ck = 0; ck < NCHUNK; ck++) {
        __syncthreads();   // protects q_sT/fac_s on first iter, tile reuse after
        const int kt0 = ck * CHUNK;
        for (int i = tid; i < CHUNK * DHEAD / 4; i += 256) {
            int j  = i / (DHEAD / 4);
            int dd = (i % (DHEAD / 4)) * 4;
            size_t gidx = ((size_t)b * SEQ + (kt0 + j)) * CDIM + h * DHEAD + dd;
            float4 kv = *(const float4*)&k[gidx];
            const int slot = j & 31, half = j >> 5;
            ((float*)&kT2[dd + 0][slot])[half] = kv.x;
            ((float*)&kT2[dd + 1][slot])[half] = kv.y;
            ((float*)&kT2[dd + 2][slot])[half] = kv.z;
            ((float*)&kT2[dd + 3][slot])[half] = kv.w;
            *(float4*)&v_s[j][dd] = *(const float4*)&v[gidx];
        }
        __syncthreads();

        // scores: lane owns keys (lane, lane+32); queries packed in f32x2
        ull s0_01 = 0, s0_23 = 0, s1_01 = 0, s1_23 = 0;
#pragma unroll 8
        for (int d = 0; d < DHEAD; d++) {
            ull kp = kT2[d][lane];
            float k0v = lo2(kp), k1v = hi2(kp);
            ull k0d = pack2(k0v, k0v), k1d = pack2(k1v, k1v);
            ull q01 = *(const ull*)&q_sT[d][qbase];
            ull q23 = *(const ull*)&q_sT[d][qbase + 2];
            s0_01 = ffma2(q01, k0d, s0_01);
            s0_23 = ffma2(q23, k0d, s0_23);
            s1_01 = ffma2(q01, k1d, s1_01);
            s1_23 = ffma2(q23, k1d, s1_23);
        }

        float s0[4] = { lo2(s0_01), hi2(s0_01), lo2(s0_23), hi2(s0_23) };
        float s1[4] = { lo2(s1_01), hi2(s1_01), lo2(s1_23), hi2(s1_23) };
        float p0[4], p1[4];

#pragma unroll
        for (int qi = 0; qi < 4; qi++) {
            float f  = fac_s[qbase + qi];
            float a0 = s0[qi] * f;
            float a1 = s1[qi] * f;

            // exact 32nd-largest of 64 via two-array bitonic split
            float hv = fmaxf(a0, a1);
            float lv = fminf(a0, a1);
#pragma unroll
            for (int kk = 2; kk <= 32; kk <<= 1) {
#pragma unroll
                for (int j = kk >> 1; j > 0; j >>= 1) {
                    bcas(hv, lane, j, kk, false);
                    bcas(lv, lane, j, kk, true);
                }
            }
            float D = fmaxf(hv, lv);
            float thr = D;
#pragma unroll
            for (int o = 16; o; o >>= 1)
                thr = fminf(thr, __shfl_xor_sync(0xffffffffu, thr, o));

            float m0 = (a0 >= thr) ? a0 : 0.f;
            float m1 = (a1 >= thr) ? a1 : 0.f;
            float mx = fmaxf(m0, m1);
#pragma unroll
            for (int o = 16; o; o >>= 1)
                mx = fmaxf(mx, __shfl_xor_sync(0xffffffffu, mx, o));
            float e0 = __expf(m0 - mx);
            float e1 = __expf(m1 - mx);
            float ds = e0 + e1;
#pragma unroll
            for (int o = 16; o; o >>= 1)
                ds += __shfl_xor_sync(0xffffffffu, ds, o);
            float inv = 1.f / ds;
            p0[qi] = e0 * inv;
            p1[qi] = e1 * inv;
        }

        // p @ v: shfl-broadcast p, packed f32x2 across query pairs
#pragma unroll 8
        for (int j = 0; j < 32; j++) {
            float2 vv = *(const float2*)&v_s[j][d0];
            ull vxd = pack2(vv.x, vv.x), vyd = pack2(vv.y, vv.y);
            ull pp01 = pack2(__shfl_sync(0xffffffffu, p0[0], j),
                             __shfl_sync(0xffffffffu, p0[1], j));
            ull pp23 = pack2(__shfl_sync(0xffffffffu, p0[2], j),
                             __shfl_sync(0xffffffffu, p0[3], j));
            acc01x = ffma2(pp01, vxd, acc01x);
            acc01y = ffma2(pp01, vyd, acc01y);
            acc23x = ffma2(pp23, vxd, acc23x);
            acc23y = ffma2(pp23, vyd, acc23y);
        }
#pragma unroll 8
        for (int j = 0; j < 32; j++) {
            float2 vv = *(const float2*)&v_s[j + 32][d0];
            ull vxd = pack2(vv.x, vv.x), vyd = pack2(vv.y, vv.y);
            ull pp01 = pack2(__shfl_sync(0xffffffffu, p1[0], j),
                             __shfl_sync(0xffffffffu, p1[1], j));
            ull pp23 = pack2(__shfl_sync(0xffffffffu, p1[2], j),
                             __shfl_sync(0xffffffffu, p1[3], j));
            acc01x = ffma2(pp01, vxd, acc01x);
            acc01y = ffma2(pp01, vyd, acc01y);
            acc23x = ffma2(pp23, vxd, acc23x);
            acc23y = ffma2(pp23, vyd, acc23y);
        }
    }

    // write [B,T,C]; normalizer sum(p) == NCHUNK == 16 exactly
    const float invn = 1.f / 16.f;
    float ox[4] = { lo2(acc01x), hi2(acc01x), lo2(acc23x), hi2(acc23x) };
    float oy[4] = { lo2(acc01y), hi2(acc01y), lo2(acc23y), hi2(acc23y) };
#pragma unroll
    for (int qi = 0; qi < 4; qi++) {
        int ql = qbase + qi;
        float2 o2 = make_float2(ox[qi] * invn, oy[qi] * invn);
        *(float2*)&out[((size_t)b * SEQ + (t0 + ql)) * CDIM + h * DHEAD + d0] = o2;
    }
}

// ---------------------------------------------------------------------------
// Launch
// ---------------------------------------------------------------------------
extern "C" void kernel_launch(void* const* d_in, const int* in_sizes, int n_in,
                              void* d_out, int out_size)
{
    const float* x    = (const float*)d_in[0];
    const float* impS = (const float*)d_in[1];
    const float* temp = (const float*)d_in[2];
    const float* Wq   = (const float*)d_in[3];
    const float* Wk   = (const float*)d_in[4];
    const float* Wv   = (const float*)d_in[5];
    const float* Wo   = (const float*)d_in[6];
    float* outp = (float*)d_out;

    float *pq, *pk, *pv, *pa;
    cudaGetSymbolAddress((void**)&pq, g_q);
    cudaGetSymbolAddress((void**)&pk, g_k);
    cudaGetSymbolAddress((void**)&pv, g_v);
    cudaGetSymbolAddress((void**)&pa, g_attn);

    const int M = BATCH * SEQ;   // 4096
    const int N = CDIM;          // 1024
    const int K = CDIM;          // 1024

    // fused QKV projection on tensor cores (grid.z selects weight/output)
    dim3 g3(N / TBN, M / TBM, 3);
    tf32gemm_kernel<<<g3, 256>>>(x, Wq, Wk, Wv, pq, pk, pv, M, N, K);

    dim3 agrid(SEQ / QB, HEADS, BATCH);
    attn_kernel<<<agrid, 256>>>(pq, pk, pv, impS, temp, pa);

    dim3 g1(N / TBN, M / TBM, 1);
    tf32gemm_kernel<<<g1, 256>>>(pa, Wo, Wo, Wo, outp, outp, outp, M, N, K);
}

// round 8
// speedup vs baseline: 1.8098x; 1.0183x over previous
#include <cuda_runtime.h>
#include <math.h>
#include <stdint.h>

typedef unsigned long long ull;

// Problem constants
#define BATCH  4
#define SEQ    1024
#define CDIM   1024
#define HEADS  16
#define DHEAD  64
#define CHUNK  64
#define NCHUNK 16
#define TOPKN  32
#define SCALEF 0.125f   // 1/sqrt(64)

// Scratch (allocation-free rule: device globals)
__device__ float g_q[BATCH*SEQ*CDIM];
__device__ float g_k[BATCH*SEQ*CDIM];
__device__ float g_v[BATCH*SEQ*CDIM];
__device__ float g_attn[BATCH*SEQ*CDIM];

// ---------------- f32x2 packed helpers (Blackwell FFMA2 path) --------------
__device__ __forceinline__ ull pack2(float lo, float hi) {
    ull r; asm("mov.b64 %0, {%1, %2};" : "=l"(r) : "f"(lo), "f"(hi)); return r;
}
__device__ __forceinline__ float lo2(ull v) {
    float a, b; asm("mov.b64 {%0, %1}, %2;" : "=f"(a), "=f"(b) : "l"(v)); return a;
}
__device__ __forceinline__ float hi2(ull v) {
    float a, b; asm("mov.b64 {%0, %1}, %2;" : "=f"(a), "=f"(b) : "l"(v)); return b;
}
__device__ __forceinline__ ull ffma2(ull a, ull b, ull c) {
    ull d; asm("fma.rn.f32x2 %0, %1, %2, %3;" : "=l"(d) : "l"(a), "l"(b), "l"(c));
    return d;
}

// ---------------------------------------------------------------------------
// TF32 tensor-core GEMM, double-buffered, paired-smem fragment layout.
// C[M,N] = A[M,K] @ B[K,N], row-major fp32. BM=BN=128, BK=16, 256 thr, 8 warps
// (2m x 4n), warp tile 64x32, 4x4 m16n8k8 mma per k8-step.
// As2[k][pid] packs rows (m, m+8); Bs2[sp][n] packs rows (k, k+4).
// blockIdx.z selects (B,C) pair -> one launch covers the Q/K/V GEMMs.
// ---------------------------------------------------------------------------
#define TBM 128
#define TBN 128
#define TBK 16

__device__ __forceinline__ uint32_t f2tf(float f) {
    uint32_t u; asm("cvt.rna.tf32.f32 %0, %1;" : "=r"(u) : "f"(f)); return u;
}
__device__ __forceinline__ ull packtf(float lo, float hi) {
    return (ull)f2tf(lo) | ((ull)f2tf(hi) << 32);
}

__device__ __forceinline__ void mma_tf32(float c[4], uint32_t a0, uint32_t a1,
                                         uint32_t a2, uint32_t a3,
                                         uint32_t b0, uint32_t b1) {
    asm volatile(
        "mma.sync.aligned.m16n8k8.row.col.f32.tf32.tf32.f32 "
        "{%0,%1,%2,%3}, {%4,%5,%6,%7}, {%8,%9}, {%0,%1,%2,%3};"
        : "+f"(c[0]), "+f"(c[1]), "+f"(c[2]), "+f"(c[3])
        : "r"(a0), "r"(a1), "r"(a2), "r"(a3), "r"(b0), "r"(b1));
}

__global__ __launch_bounds__(256, 2)
void tf32gemm_kernel(const float* __restrict__ A,
                     const float* __restrict__ B0, const float* __restrict__ B1,
                     const float* __restrict__ B2,
                     float* __restrict__ C0, float* __restrict__ C1,
                     float* __restrict__ C2,
                     int M, int N, int K)
{
    const int z = blockIdx.z;
    const float* B = (z == 0) ? B0 : ((z == 1) ? B1 : B2);
    float*       C = (z == 0) ? C0 : ((z == 1) ? C1 : C2);

    // pair layouts, double buffered
    __shared__ ull As2[2][TBK][64 + 2];   // (m, m+8) pairs   2 x 8.25 KB
    __shared__ ull Bs2[2][8][TBN + 2];    // (k, k+4) pairs   2 x 8.1 KB

    const int tid  = threadIdx.x;
    const int lane = tid & 31;
    const int wid  = tid >> 5;
    const int bx = blockIdx.x, by = blockIdx.y;

    const int g = lane >> 2;        // 0..7
    const int t = lane & 3;         // 0..3
    const int wm = (wid & 1) * 64;
    const int wn = (wid >> 1) * 32;
    const int rb0 = wm >> 4;        // row-block base (0 or 4)

    // A staging: pair pid (0..63) -> rows (am, am+8); kh (0..3) -> k cols kh*4..+3
    const int pid = tid & 63;
    const int kh  = tid >> 6;
    const int am  = ((pid >> 3) << 4) + (pid & 7);
    // B staging: rp (0..7) -> row pair (bk, bk+4); cols bc..bc+3
    const int rp  = tid >> 5;
    const int bk  = (rp & 3) + ((rp >> 2) << 3);
    const int bc  = (tid & 31) * 4;

    const float* Ap0 = A + (size_t)(by * TBM + am) * K + kh * 4;
    const float* Ap1 = Ap0 + (size_t)8 * K;
    const float* Bp0 = B + (size_t)bk * N + bx * TBN + bc;
    const float* Bp1 = Bp0 + (size_t)4 * N;

    float c[4][4][4];
#pragma unroll
    for (int i = 0; i < 4; i++)
#pragma unroll
        for (int j = 0; j < 4; j++)
#pragma unroll
            for (int e = 0; e < 4; e++) c[i][j][e] = 0.f;

    const int NT = K / TBK;   // 64

    // prefetch tile 0
    float4 ra0 = *(const float4*)Ap0;
    float4 ra1 = *(const float4*)Ap1;
    float4 rb_ = *(const float4*)Bp0;
    float4 rb2 = *(const float4*)Bp1;
    {
        As2[0][kh * 4 + 0][pid] = packtf(ra0.x, ra1.x);
        As2[0][kh * 4 + 1][pid] = packtf(ra0.y, ra1.y);
        As2[0][kh * 4 + 2][pid] = packtf(ra0.z, ra1.z);
        As2[0][kh * 4 + 3][pid] = packtf(ra0.w, ra1.w);
        Bs2[0][rp][bc + 0] = packtf(rb_.x, rb2.x);
        Bs2[0][rp][bc + 1] = packtf(rb_.y, rb2.y);
        Bs2[0][rp][bc + 2] = packtf(rb_.z, rb2.z);
        Bs2[0][rp][bc + 3] = packtf(rb_.w, rb2.w);
    }
    __syncthreads();

    for (int kt = 0; kt < NT; kt++) {
        const int cur = kt & 1;
        if (kt + 1 < NT) {
            ra0 = *(const float4*)(Ap0 + (kt + 1) * TBK);
            ra1 = *(const float4*)(Ap1 + (kt + 1) * TBK);
            rb_ = *(const float4*)(Bp0 + (size_t)(kt + 1) * TBK * N);
            rb2 = *(const float4*)(Bp1 + (size_t)(kt + 1) * TBK * N);
        }

#pragma unroll
        for (int s = 0; s < 2; s++) {
            const int kA = s * 8 + t;
            const int sp = s * 4 + t;
            uint32_t af[4][4];
#pragma unroll
            for (int i = 0; i < 4; i++) {
                const int pi = (rb0 + i) * 8 + g;
                ull v0 = As2[cur][kA][pi];
                ull v1 = As2[cur][kA + 4][pi];
                af[i][0] = (uint32_t)v0; af[i][1] = (uint32_t)(v0 >> 32);
                af[i][2] = (uint32_t)v1; af[i][3] = (uint32_t)(v1 >> 32);
            }
            uint32_t bf[4][2];
#pragma unroll
            for (int j = 0; j < 4; j++) {
                ull v = Bs2[cur][sp][wn + j * 8 + g];
                bf[j][0] = (uint32_t)v; bf[j][1] = (uint32_t)(v >> 32);
            }
#pragma unroll
            for (int i = 0; i < 4; i++)
#pragma unroll
                for (int j = 0; j < 4; j++)
                    mma_tf32(c[i][j], af[i][0], af[i][1], af[i][2], af[i][3],
                             bf[j][0], bf[j][1]);
        }

        if (kt + 1 < NT) {
            const int nxt = cur ^ 1;
            As2[nxt][kh * 4 + 0][pid] = packtf(ra0.x, ra1.x);
            As2[nxt][kh * 4 + 1][pid] = packtf(ra0.y, ra1.y);
            As2[nxt][kh * 4 + 2][pid] = packtf(ra0.z, ra1.z);
            As2[nxt][kh * 4 + 3][pid] = packtf(ra0.w, ra1.w);
            Bs2[nxt][rp][bc + 0] = packtf(rb_.x, rb2.x);
            Bs2[nxt][rp][bc + 1] = packtf(rb_.y, rb2.y);
            Bs2[nxt][rp][bc + 2] = packtf(rb_.z, rb2.z);
            Bs2[nxt][rp][bc + 3] = packtf(rb_.w, rb2.w);
            __syncthreads();
        }
    }

    // epilogue: thread owns (rows g, g+8) x (cols 2t, 2t+1) per tile
#pragma unroll
    for (int i = 0; i < 4; i++) {
        const int row = by * TBM + wm + i * 16 + g;
#pragma unroll
        for (int j = 0; j < 4; j++) {
            const int col = bx * TBN + wn + j * 8 + 2 * t;
            *(float2*)&C[(size_t)row * N + col]       = make_float2(c[i][j][0], c[i][j][1]);
            *(float2*)&C[(size_t)(row + 8) * N + col] = make_float2(c[i][j][2], c[i][j][3]);
        }
    }
}

// ---------------------------------------------------------------------------
// Sparse chunked attention.
// Grid: (SEQ/32, HEADS, BATCH); 256 threads (8 warps); warp handles 4 queries.
// Scores: packed f32x2 FMA, q via broadcast LDS128. Exact 32nd-largest via
// two-array bitonic split. Softmax over all 64 (zeros included).
// PV: p staged in smem (2 STS128), broadcast LDS128 p + LDS64 v from smem.
// Numerically identical to round-7 kernel (same ops, same order).
// ---------------------------------------------------------------------------
#define QB 32

__device__ __forceinline__ void bcas(float& x, int i, int j, int k, bool desc) {
    float pv = __shfl_xor_sync(0xffffffffu, x, j);
    bool keep_min = (((i & j) == 0) == ((((i & k) == 0) ? 1 : 0) ^ (desc ? 1 : 0)));
    x = keep_min ? fminf(x, pv) : fmaxf(x, pv);
}

__global__ __launch_bounds__(256)
void attn_kernel(const float* __restrict__ q, const float* __restrict__ k,
                 const float* __restrict__ v, const float* __restrict__ imp,
                 const float* __restrict__ temps, float* __restrict__ out)
{
    __shared__ float q_sT[DHEAD][QB];          // transposed queries, 8 KB
    __shared__ ull   kT2[DHEAD][CHUNK / 2];    // key pairs (j, j+32), 16 KB
    __shared__ float v_s[CHUNK][DHEAD];        // 16 KB
    __shared__ float p_s[8][CHUNK][4];         // [warp][key][query], 8 KB
    __shared__ float fac_s[QB];

    const int b  = blockIdx.z;
    const int h  = blockIdx.y;
    const int t0 = blockIdx.x * QB;
    const int tid  = threadIdx.x;
    const int lane = tid & 31;
    const int wid  = tid >> 5;

    // per-query factor: SCALE / clip(temp) * sigmoid((sigmoid(imp)-0.5)*10)
    if (tid < QB) {
        float tmp = temps[b * HEADS + h];
        tmp = fminf(fmaxf(tmp, 0.1f), 100.f);
        float is = imp[((size_t)b * SEQ + (t0 + tid)) * HEADS + h];
        float ip = 1.f / (1.f + expf(-is));
        float mw = 1.f / (1.f + expf(-((ip - 0.5f) * 10.f)));
        fac_s[tid] = (SCALEF / tmp) * mw;
    }

    // load 32 queries (transposed: q_sT[d][query])
    for (int i = tid; i < QB * DHEAD / 4; i += 256) {
        int qq = i / (DHEAD / 4);
        int dd = (i % (DHEAD / 4)) * 4;
        float4 qv = *(const float4*)&q[((size_t)b * SEQ + (t0 + qq)) * CDIM + h * DHEAD + dd];
        q_sT[dd + 0][qq] = qv.x;
        q_sT[dd + 1][qq] = qv.y;
        q_sT[dd + 2][qq] = qv.z;
        q_sT[dd + 3][qq] = qv.w;
    }

    ull acc2[4] = {0ull, 0ull, 0ull, 0ull};    // per query, dims (d0, d0+1)
    const int d0 = lane * 2;
    const int qbase = wid * 4;

    for (int ck = 0; ck < NCHUNK; ck++) {
        __syncthreads();   // protects q_sT/fac_s first iter, tile reuse after
        const int kt0 = ck * CHUNK;
        for (int i = tid; i < CHUNK * DHEAD / 4; i += 256) {
            int j  = i / (DHEAD / 4);
            int dd = (i % (DHEAD / 4)) * 4;
            size_t gidx = ((size_t)b * SEQ + (kt0 + j)) * CDIM + h * DHEAD + dd;
            float4 kv = *(const float4*)&k[gidx];
            const int slot = j & 31, half = j >> 5;
            ((float*)&kT2[dd + 0][slot])[half] = kv.x;
            ((float*)&kT2[dd + 1][slot])[half] = kv.y;
            ((float*)&kT2[dd + 2][slot])[half] = kv.z;
            ((float*)&kT2[dd + 3][slot])[half] = kv.w;
            *(float4*)&v_s[j][dd] = *(const float4*)&v[gidx];
        }
        __syncthreads();

        // scores: lane owns keys (lane, lane+32); queries packed in f32x2
        ull s0_01 = 0, s0_23 = 0, s1_01 = 0, s1_23 = 0;
#pragma unroll 8
        for (int d = 0; d < DHEAD; d++) {
            ull kp = kT2[d][lane];
            float4 qv = *(const float4*)&q_sT[d][qbase];   // broadcast LDS128
            float k0v = lo2(kp), k1v = hi2(kp);
            ull k0d = pack2(k0v, k0v), k1d = pack2(k1v, k1v);
            ull q01 = pack2(qv.x, qv.y);
            ull q23 = pack2(qv.z, qv.w);
            s0_01 = ffma2(q01, k0d, s0_01);
            s0_23 = ffma2(q23, k0d, s0_23);
            s1_01 = ffma2(q01, k1d, s1_01);
            s1_23 = ffma2(q23, k1d, s1_23);
        }

        float s0[4] = { lo2(s0_01), hi2(s0_01), lo2(s0_23), hi2(s0_23) };
        float s1[4] = { lo2(s1_01), hi2(s1_01), lo2(s1_23), hi2(s1_23) };
        float p0[4], p1[4];

#pragma unroll
        for (int qi = 0; qi < 4; qi++) {
            float f  = fac_s[qbase + qi];
            float a0 = s0[qi] * f;
            float a1 = s1[qi] * f;

            // exact 32nd-largest of 64 via two-array bitonic split
            float hv = fmaxf(a0, a1);
            float lv = fminf(a0, a1);
#pragma unroll
            for (int kk = 2; kk <= 32; kk <<= 1) {
#pragma unroll
                for (int j = kk >> 1; j > 0; j >>= 1) {
                    bcas(hv, lane, j, kk, false);
                    bcas(lv, lane, j, kk, true);
                }
            }
            float D = fmaxf(hv, lv);
            float thr = D;
#pragma unroll
            for (int o = 16; o; o >>= 1)
                thr = fminf(thr, __shfl_xor_sync(0xffffffffu, thr, o));

            float m0 = (a0 >= thr) ? a0 : 0.f;
            float m1 = (a1 >= thr) ? a1 : 0.f;
            float mx = fmaxf(m0, m1);
#pragma unroll
            for (int o = 16; o; o >>= 1)
                mx = fmaxf(mx, __shfl_xor_sync(0xffffffffu, mx, o));
            float e0 = __expf(m0 - mx);
            float e1 = __expf(m1 - mx);
            float ds = e0 + e1;
#pragma unroll
            for (int o = 16; o; o >>= 1)
                ds += __shfl_xor_sync(0xffffffffu, ds, o);
            float inv = 1.f / ds;
            p0[qi] = e0 * inv;
            p1[qi] = e1 * inv;
        }

        // stage p to smem (warp-private), then PV with broadcast LDS128 p
        *(float4*)&p_s[wid][lane][0]      = make_float4(p0[0], p0[1], p0[2], p0[3]);
        *(float4*)&p_s[wid][lane + 32][0] = make_float4(p1[0], p1[1], p1[2], p1[3]);
        __syncwarp();

#pragma unroll 8
        for (int j = 0; j < CHUNK; j++) {
            float4 pj = *(const float4*)&p_s[wid][j][0];   // broadcast
            float2 vv = *(const float2*)&v_s[j][d0];
            ull v2 = pack2(vv.x, vv.y);
            acc2[0] = ffma2(pack2(pj.x, pj.x), v2, acc2[0]);
            acc2[1] = ffma2(pack2(pj.y, pj.y), v2, acc2[1]);
            acc2[2] = ffma2(pack2(pj.z, pj.z), v2, acc2[2]);
            acc2[3] = ffma2(pack2(pj.w, pj.w), v2, acc2[3]);
        }
        __syncwarp();   // keep p_s stable until all lanes done reading
    }

    // write [B,T,C]; normalizer sum(p) == NCHUNK == 16 exactly
    const float invn = 1.f / 16.f;
#pragma unroll
    for (int qi = 0; qi < 4; qi++) {
        int ql = qbase + qi;
        float2 o2 = make_float2(lo2(acc2[qi]) * invn, hi2(acc2[qi]) * invn);
        *(float2*)&out[((size_t)b * SEQ + (t0 + ql)) * CDIM + h * DHEAD + d0] = o2;
    }
}

// ---------------------------------------------------------------------------
// Launch
// ---------------------------------------------------------------------------
extern "C" void kernel_launch(void* const* d_in, const int* in_sizes, int n_in,
                              void* d_out, int out_size)
{
    const float* x    = (const float*)d_in[0];
    const float* impS = (const float*)d_in[1];
    const float* temp = (const float*)d_in[2];
    const float* Wq   = (const float*)d_in[3];
    const float* Wk   = (const float*)d_in[4];
    const float* Wv   = (const float*)d_in[5];
    const float* Wo   = (const float*)d_in[6];
    float* outp = (float*)d_out;

    float *pq, *pk, *pv, *pa;
    cudaGetSymbolAddress((void**)&pq, g_q);
    cudaGetSymbolAddress((void**)&pk, g_k);
    cudaGetSymbolAddress((void**)&pv, g_v);
    cudaGetSymbolAddress((void**)&pa, g_attn);

    const int M = BATCH * SEQ;   // 4096
    const int N = CDIM;          // 1024
    const int K = CDIM;          // 1024

    // fused QKV projection on tensor cores (grid.z selects weight/output)
    dim3 g3(N / TBN, M / TBM, 3);
    tf32gemm_kernel<<<g3, 256>>>(x, Wq, Wk, Wv, pq, pk, pv, M, N, K);

    dim3 agrid(SEQ / QB, HEADS, BATCH);
    attn_kernel<<<agrid, 256>>>(pq, pk, pv, impS, temp, pa);

    dim3 g1(N / TBN, M / TBM, 1);
    tf32gemm_kernel<<<g1, 256>>>(pa, Wo, Wo, Wo, outp, outp, outp, M, N, K);
}

// round 9
// speedup vs baseline: 2.1159x; 1.1691x over previous
#include <cuda_runtime.h>
#include <math.h>
#include <stdint.h>

typedef unsigned long long ull;

// Problem constants
#define BATCH  4
#define SEQ    1024
#define CDIM   1024
#define HEADS  16
#define DHEAD  64
#define CHUNK  64
#define NCHUNK 16
#define TOPKN  32
#define SCALEF 0.125f   // 1/sqrt(64)

// Scratch (allocation-free rule: device globals)
__device__ float g_q[BATCH*SEQ*CDIM];
__device__ float g_k[BATCH*SEQ*CDIM];
__device__ float g_v[BATCH*SEQ*CDIM];
__device__ float g_attn[BATCH*SEQ*CDIM];

// ---------------- f32x2 packed helpers (Blackwell FFMA2 path) --------------
__device__ __forceinline__ ull pack2(float lo, float hi) {
    ull r; asm("mov.b64 %0, {%1, %2};" : "=l"(r) : "f"(lo), "f"(hi)); return r;
}
__device__ __forceinline__ float lo2(ull v) {
    float a, b; asm("mov.b64 {%0, %1}, %2;" : "=f"(a), "=f"(b) : "l"(v)); return a;
}
__device__ __forceinline__ float hi2(ull v) {
    float a, b; asm("mov.b64 {%0, %1}, %2;" : "=f"(a), "=f"(b) : "l"(v)); return b;
}
__device__ __forceinline__ ull ffma2(ull a, ull b, ull c) {
    ull d; asm("fma.rn.f32x2 %0, %1, %2, %3;" : "=l"(d) : "l"(a), "l"(b), "l"(c));
    return d;
}

// ---------------------------------------------------------------------------
// TF32 tensor-core GEMM, warp tile 64x64, double-buffered pair-smem.
// C[M,N] = A[M,K] @ B[K,N], row-major fp32. BM=128, BN=256, BK=16, 256 thr,
// 8 warps (2m x 4n). Per warp per k8: 4 m-tiles x 8 n-tiles m16n8k8 = 32 MMA,
// 16 LDS64 (conflict-free via padded strides 72 / 264).
// As2[k][pid] packs rows (m, m+8); Bs2[sp][n] packs rows (k, k+4).
// blockIdx.z selects (B,C) pair -> one launch covers the Q/K/V GEMMs.
// ---------------------------------------------------------------------------
#define TBM 128
#define TBN 256
#define TBK 16
#define APAD 72    // 64 + 8  -> (t*72+g) distinct mod 32
#define BPAD 264   // 256 + 8 -> (t*264+g) distinct mod 32

__device__ __forceinline__ uint32_t f2tf(float f) {
    uint32_t u; asm("cvt.rna.tf32.f32 %0, %1;" : "=r"(u) : "f"(f)); return u;
}
__device__ __forceinline__ ull packtf(float lo, float hi) {
    return (ull)f2tf(lo) | ((ull)f2tf(hi) << 32);
}

__device__ __forceinline__ void mma_tf32(float c[4], uint32_t a0, uint32_t a1,
                                         uint32_t a2, uint32_t a3,
                                         uint32_t b0, uint32_t b1) {
    asm volatile(
        "mma.sync.aligned.m16n8k8.row.col.f32.tf32.tf32.f32 "
        "{%0,%1,%2,%3}, {%4,%5,%6,%7}, {%8,%9}, {%0,%1,%2,%3};"
        : "+f"(c[0]), "+f"(c[1]), "+f"(c[2]), "+f"(c[3])
        : "r"(a0), "r"(a1), "r"(a2), "r"(a3), "r"(b0), "r"(b1));
}

__global__ __launch_bounds__(256, 1)
void tf32gemm_kernel(const float* __restrict__ A,
                     const float* __restrict__ B0, const float* __restrict__ B1,
                     const float* __restrict__ B2,
                     float* __restrict__ C0, float* __restrict__ C1,
                     float* __restrict__ C2,
                     int M, int N, int K)
{
    const int z = blockIdx.z;
    const float* B = (z == 0) ? B0 : ((z == 1) ? B1 : B2);
    float*       C = (z == 0) ? C0 : ((z == 1) ? C1 : C2);

    __shared__ ull As2[2][TBK][APAD];   // (m, m+8) pairs
    __shared__ ull Bs2[2][8][BPAD];     // (k, k+4) pairs

    const int tid  = threadIdx.x;
    const int lane = tid & 31;
    const int wid  = tid >> 5;
    const int bx = blockIdx.x, by = blockIdx.y;

    const int g = lane >> 2;        // 0..7
    const int t = lane & 3;         // 0..3
    const int wm = (wid & 1) * 64;
    const int wn = (wid >> 1) * 64;
    const int rb0 = wm >> 4;        // 0 or 4

    // A staging: pair pid (0..63) -> rows (am, am+8); kh (0..3) -> k quad
    const int pid = tid & 63;
    const int kh  = tid >> 6;
    const int am  = ((pid >> 3) << 4) + (pid & 7);
    // B staging: rp (0..7) -> row pair (bk, bk+4); cols bc..bc+7
    const int rp  = tid >> 5;
    const int bk  = (rp & 3) + ((rp >> 2) << 3);
    const int bc  = (tid & 31) * 8;

    const float* Ap0 = A + (size_t)(by * TBM + am) * K + kh * 4;
    const float* Ap1 = Ap0 + (size_t)8 * K;
    const float* Bp  = B + (size_t)bk * N + bx * TBN + bc;

    float c[4][8][4];
#pragma unroll
    for (int i = 0; i < 4; i++)
#pragma unroll
        for (int j = 0; j < 8; j++)
#pragma unroll
            for (int e = 0; e < 4; e++) c[i][j][e] = 0.f;

    const int NT = K / TBK;   // 64

    // prefetch tile 0
    float4 ra0 = *(const float4*)Ap0;
    float4 ra1 = *(const float4*)Ap1;
    float4 rb0_ = *(const float4*)Bp;
    float4 rb1_ = *(const float4*)(Bp + 4);
    float4 rb2_ = *(const float4*)(Bp + (size_t)4 * N);
    float4 rb3_ = *(const float4*)(Bp + (size_t)4 * N + 4);
    {
        As2[0][kh * 4 + 0][pid] = packtf(ra0.x, ra1.x);
        As2[0][kh * 4 + 1][pid] = packtf(ra0.y, ra1.y);
        As2[0][kh * 4 + 2][pid] = packtf(ra0.z, ra1.z);
        As2[0][kh * 4 + 3][pid] = packtf(ra0.w, ra1.w);
        Bs2[0][rp][bc + 0] = packtf(rb0_.x, rb2_.x);
        Bs2[0][rp][bc + 1] = packtf(rb0_.y, rb2_.y);
        Bs2[0][rp][bc + 2] = packtf(rb0_.z, rb2_.z);
        Bs2[0][rp][bc + 3] = packtf(rb0_.w, rb2_.w);
        Bs2[0][rp][bc + 4] = packtf(rb1_.x, rb3_.x);
        Bs2[0][rp][bc + 5] = packtf(rb1_.y, rb3_.y);
        Bs2[0][rp][bc + 6] = packtf(rb1_.z, rb3_.z);
        Bs2[0][rp][bc + 7] = packtf(rb1_.w, rb3_.w);
    }
    __syncthreads();

    for (int kt = 0; kt < NT; kt++) {
        const int cur = kt & 1;
        if (kt + 1 < NT) {
            ra0  = *(const float4*)(Ap0 + (kt + 1) * TBK);
            ra1  = *(const float4*)(Ap1 + (kt + 1) * TBK);
            const float* Bn = Bp + (size_t)(kt + 1) * TBK * N;
            rb0_ = *(const float4*)Bn;
            rb1_ = *(const float4*)(Bn + 4);
            rb2_ = *(const float4*)(Bn + (size_t)4 * N);
            rb3_ = *(const float4*)(Bn + (size_t)4 * N + 4);
        }

#pragma unroll
        for (int s = 0; s < 2; s++) {
            const int kA = s * 8 + t;
            const int sp = s * 4 + t;
            uint32_t af[4][4];
#pragma unroll
            for (int i = 0; i < 4; i++) {
                const int pi = (rb0 + i) * 8 + g;
                ull v0 = As2[cur][kA][pi];
                ull v1 = As2[cur][kA + 4][pi];
                af[i][0] = (uint32_t)v0; af[i][1] = (uint32_t)(v0 >> 32);
                af[i][2] = (uint32_t)v1; af[i][3] = (uint32_t)(v1 >> 32);
            }
            uint32_t bf[8][2];
#pragma unroll
            for (int j = 0; j < 8; j++) {
                ull v = Bs2[cur][sp][wn + j * 8 + g];
                bf[j][0] = (uint32_t)v; bf[j][1] = (uint32_t)(v >> 32);
            }
#pragma unroll
            for (int i = 0; i < 4; i++)
#pragma unroll
                for (int j = 0; j < 8; j++)
                    mma_tf32(c[i][j], af[i][0], af[i][1], af[i][2], af[i][3],
                             bf[j][0], bf[j][1]);
        }

        if (kt + 1 < NT) {
            const int nxt = cur ^ 1;
            As2[nxt][kh * 4 + 0][pid] = packtf(ra0.x, ra1.x);
            As2[nxt][kh * 4 + 1][pid] = packtf(ra0.y, ra1.y);
            As2[nxt][kh * 4 + 2][pid] = packtf(ra0.z, ra1.z);
            As2[nxt][kh * 4 + 3][pid] = packtf(ra0.w, ra1.w);
            Bs2[nxt][rp][bc + 0] = packtf(rb0_.x, rb2_.x);
            Bs2[nxt][rp][bc + 1] = packtf(rb0_.y, rb2_.y);
            Bs2[nxt][rp][bc + 2] = packtf(rb0_.z, rb2_.z);
            Bs2[nxt][rp][bc + 3] = packtf(rb0_.w, rb2_.w);
            Bs2[nxt][rp][bc + 4] = packtf(rb1_.x, rb3_.x);
            Bs2[nxt][rp][bc + 5] = packtf(rb1_.y, rb3_.y);
            Bs2[nxt][rp][bc + 6] = packtf(rb1_.z, rb3_.z);
            Bs2[nxt][rp][bc + 7] = packtf(rb1_.w, rb3_.w);
            __syncthreads();
        }
    }

    // epilogue: thread owns (rows g, g+8) x (cols 2t, 2t+1) per tile
#pragma unroll
    for (int i = 0; i < 4; i++) {
        const int row = by * TBM + wm + i * 16 + g;
#pragma unroll
        for (int j = 0; j < 8; j++) {
            const int col = bx * TBN + wn + j * 8 + 2 * t;
            *(float2*)&C[(size_t)row * N + col]       = make_float2(c[i][j][0], c[i][j][1]);
            *(float2*)&C[(size_t)(row + 8) * N + col] = make_float2(c[i][j][2], c[i][j][3]);
        }
    }
}

// ---------------------------------------------------------------------------
// Sparse chunked attention (numerics identical to round 8).
// Grid: (SEQ/32, HEADS, BATCH); 256 threads (8 warps); warp handles 4 queries.
// kT2 now staged via key-pair loads: thread loads rows (j, j+32) and writes
// 4 conflict-free STS64 pairs (replaces 16 scattered STS32 per thread).
// ---------------------------------------------------------------------------
#define QB 32

__device__ __forceinline__ void bcas(float& x, int i, int j, int k, bool desc) {
    float pv = __shfl_xor_sync(0xffffffffu, x, j);
    bool keep_min = (((i & j) == 0) == ((((i & k) == 0) ? 1 : 0) ^ (desc ? 1 : 0)));
    x = keep_min ? fminf(x, pv) : fmaxf(x, pv);
}

__global__ __launch_bounds__(256)
void attn_kernel(const float* __restrict__ q, const float* __restrict__ k,
                 const float* __restrict__ v, const float* __restrict__ imp,
                 const float* __restrict__ temps, float* __restrict__ out)
{
    __shared__ float q_sT[DHEAD][QB];          // transposed queries, 8 KB
    __shared__ ull   kT2[DHEAD][CHUNK / 2];    // key pairs (j, j+32), 16 KB
    __shared__ float v_s[CHUNK][DHEAD];        // 16 KB
    __shared__ float p_s[8][CHUNK][4];         // [warp][key][query], 8 KB
    __shared__ float fac_s[QB];

    const int b  = blockIdx.z;
    const int h  = blockIdx.y;
    const int t0 = blockIdx.x * QB;
    const int tid  = threadIdx.x;
    const int lane = tid & 31;
    const int wid  = tid >> 5;

    // per-query factor: SCALE / clip(temp) * sigmoid((sigmoid(imp)-0.5)*10)
    if (tid < QB) {
        float tmp = temps[b * HEADS + h];
        tmp = fminf(fmaxf(tmp, 0.1f), 100.f);
        float is = imp[((size_t)b * SEQ + (t0 + tid)) * HEADS + h];
        float ip = 1.f / (1.f + expf(-is));
        float mw = 1.f / (1.f + expf(-((ip - 0.5f) * 10.f)));
        fac_s[tid] = (SCALEF / tmp) * mw;
    }

    // load 32 queries (transposed: q_sT[d][query])
    for (int i = tid; i < QB * DHEAD / 4; i += 256) {
        int qq = i / (DHEAD / 4);
        int dd = (i % (DHEAD / 4)) * 4;
        float4 qv = *(const float4*)&q[((size_t)b * SEQ + (t0 + qq)) * CDIM + h * DHEAD + dd];
        q_sT[dd + 0][qq] = qv.x;
        q_sT[dd + 1][qq] = qv.y;
        q_sT[dd + 2][qq] = qv.z;
        q_sT[dd + 3][qq] = qv.w;
    }

    ull acc2[4] = {0ull, 0ull, 0ull, 0ull};    // per query, dims (d0, d0+1)
    const int d0 = lane * 2;
    const int qbase = wid * 4;

    for (int ck = 0; ck < NCHUNK; ck++) {
        __syncthreads();   // protects q_sT/fac_s first iter, tile reuse after
        const int kt0 = ck * CHUNK;

        // K: pair staging. unit u -> (slot = u&31, d-quad = u>>5)
        const float* kb = &k[((size_t)b * SEQ + kt0) * CDIM + h * DHEAD];
#pragma unroll
        for (int u = tid; u < 512; u += 256) {
            const int slot = u & 31;
            const int dq   = (u >> 5) * 4;
            const float* k0p = kb + (size_t)slot * CDIM + dq;
            float4 k0 = *(const float4*)k0p;
            float4 k1 = *(const float4*)(k0p + (size_t)32 * CDIM);
            kT2[dq + 0][slot] = pack2(k0.x, k1.x);
            kT2[dq + 1][slot] = pack2(k0.y, k1.y);
            kT2[dq + 2][slot] = pack2(k0.z, k1.z);
            kT2[dq + 3][slot] = pack2(k0.w, k1.w);
        }
        // V: float4 staging
#pragma unroll
        for (int i = tid; i < CHUNK * DHEAD / 4; i += 256) {
            int j  = i >> 4;
            int dd = (i & 15) * 4;
            *(float4*)&v_s[j][dd] =
                *(const float4*)&v[((size_t)b * SEQ + (kt0 + j)) * CDIM + h * DHEAD + dd];
        }
        __syncthreads();

        // scores: lane owns keys (lane, lane+32); queries packed in f32x2
        ull s0_01 = 0, s0_23 = 0, s1_01 = 0, s1_23 = 0;
#pragma unroll 8
        for (int d = 0; d < DHEAD; d++) {
            ull kp = kT2[d][lane];
            float4 qv = *(const float4*)&q_sT[d][qbase];   // broadcast LDS128
            float k0v = lo2(kp), k1v = hi2(kp);
            ull k0d = pack2(k0v, k0v), k1d = pack2(k1v, k1v);
            ull q01 = pack2(qv.x, qv.y);
            ull q23 = pack2(qv.z, qv.w);
            s0_01 = ffma2(q01, k0d, s0_01);
            s0_23 = ffma2(q23, k0d, s0_23);
            s1_01 = ffma2(q01, k1d, s1_01);
            s1_23 = ffma2(q23, k1d, s1_23);
        }

        float s0[4] = { lo2(s0_01), hi2(s0_01), lo2(s0_23), hi2(s0_23) };
        float s1[4] = { lo2(s1_01), hi2(s1_01), lo2(s1_23), hi2(s1_23) };
        float p0[4], p1[4];

#pragma unroll
        for (int qi = 0; qi < 4; qi++) {
            float f  = fac_s[qbase + qi];
            float a0 = s0[qi] * f;
            float a1 = s1[qi] * f;

            // exact 32nd-largest of 64 via two-array bitonic split
            float hv = fmaxf(a0, a1);
            float lv = fminf(a0, a1);
#pragma unroll
            for (int kk = 2; kk <= 32; kk <<= 1) {
#pragma unroll
                for (int j = kk >> 1; j > 0; j >>= 1) {
                    bcas(hv, lane, j, kk, false);
                    bcas(lv, lane, j, kk, true);
                }
            }
            float D = fmaxf(hv, lv);
            float thr = D;
#pragma unroll
            for (int o = 16; o; o >>= 1)
                thr = fminf(thr, __shfl_xor_sync(0xffffffffu, thr, o));

            float m0 = (a0 >= thr) ? a0 : 0.f;
            float m1 = (a1 >= thr) ? a1 : 0.f;
            float mx = fmaxf(m0, m1);
#pragma unroll
            for (int o = 16; o; o >>= 1)
                mx = fmaxf(mx, __shfl_xor_sync(0xffffffffu, mx, o));
            float e0 = __expf(m0 - mx);
            float e1 = __expf(m1 - mx);
            float ds = e0 + e1;
#pragma unroll
            for (int o = 16; o; o >>= 1)
                ds += __shfl_xor_sync(0xffffffffu, ds, o);
            float inv = 1.f / ds;
            p0[qi] = e0 * inv;
            p1[qi] = e1 * inv;
        }

        // stage p to smem (warp-private), then PV with broadcast LDS128 p
        *(float4*)&p_s[wid][lane][0]      = make_float4(p0[0], p0[1], p0[2], p0[3]);
        *(float4*)&p_s[wid][lane + 32][0] = make_float4(p1[0], p1[1], p1[2], p1[3]);
        __syncwarp();

#pragma unroll 8
        for (int j = 0; j < CHUNK; j++) {
            float4 pj = *(const float4*)&p_s[wid][j][0];   // broadcast
            float2 vv = *(const float2*)&v_s[j][d0];
            ull v2 = pack2(vv.x, vv.y);
            acc2[0] = ffma2(pack2(pj.x, pj.x), v2, acc2[0]);
            acc2[1] = ffma2(pack2(pj.y, pj.y), v2, acc2[1]);
            acc2[2] = ffma2(pack2(pj.z, pj.z), v2, acc2[2]);
            acc2[3] = ffma2(pack2(pj.w, pj.w), v2, acc2[3]);
        }
        __syncwarp();   // keep p_s stable until all lanes done reading
    }

    // write [B,T,C]; normalizer sum(p) == NCHUNK == 16 exactly
    const float invn = 1.f / 16.f;
#pragma unroll
    for (int qi = 0; qi < 4; qi++) {
        int ql = qbase + qi;
        float2 o2 = make_float2(lo2(acc2[qi]) * invn, hi2(acc2[qi]) * invn);
        *(float2*)&out[((size_t)b * SEQ + (t0 + ql)) * CDIM + h * DHEAD + d0] = o2;
    }
}

// ---------------------------------------------------------------------------
// Launch
// ---------------------------------------------------------------------------
extern "C" void kernel_launch(void* const* d_in, const int* in_sizes, int n_in,
                              void* d_out, int out_size)
{
    const float* x    = (const float*)d_in[0];
    const float* impS = (const float*)d_in[1];
    const float* temp = (const float*)d_in[2];
    const float* Wq   = (const float*)d_in[3];
    const float* Wk   = (const float*)d_in[4];
    const float* Wv   = (const float*)d_in[5];
    const float* Wo   = (const float*)d_in[6];
    float* outp = (float*)d_out;

    float *pq, *pk, *pv, *pa;
    cudaGetSymbolAddress((void**)&pq, g_q);
    cudaGetSymbolAddress((void**)&pk, g_k);
    cudaGetSymbolAddress((void**)&pv, g_v);
    cudaGetSymbolAddress((void**)&pa, g_attn);

    const int M = BATCH * SEQ;   // 4096
    const int N = CDIM;          // 1024
    const int K = CDIM;          // 1024

    // fused QKV projection on tensor cores (grid.z selects weight/output)
    dim3 g3(N / TBN, M / TBM, 3);
    tf32gemm_kernel<<<g3, 256>>>(x, Wq, Wk, Wv, pq, pk, pv, M, N, K);

    dim3 agrid(SEQ / QB, HEADS, BATCH);
    attn_kernel<<<agrid, 256>>>(pq, pk, pv, impS, temp, pa);

    dim3 g1(N / TBN, M / TBM, 1);
    tf32gemm_kernel<<<g1, 256>>>(pa, Wo, Wo, Wo, outp, outp, outp, M, N, K);
}

// round 14
// speedup vs baseline: 2.3861x; 1.1277x over previous
#include <cuda_runtime.h>
#include <math.h>
#include <stdint.h>

typedef unsigned long long ull;

// Problem constants
#define BATCH  4
#define SEQ    1024
#define CDIM   1024
#define HEADS  16
#define DHEAD  64
#define CHUNK  64
#define NCHUNK 16
#define TOPKN  32
#define SCALEF 0.125f   // 1/sqrt(64)

// Scratch (allocation-free rule: device globals)
__device__ float g_q[BATCH*SEQ*CDIM];
__device__ float g_k[BATCH*SEQ*CDIM];
__device__ float g_v[BATCH*SEQ*CDIM];
__device__ float g_attn[BATCH*SEQ*CDIM];

// ---------------- f32x2 packed helpers (Blackwell FFMA2 path) --------------
__device__ __forceinline__ ull pack2(float lo, float hi) {
    ull r; asm("mov.b64 %0, {%1, %2};" : "=l"(r) : "f"(lo), "f"(hi)); return r;
}
__device__ __forceinline__ float lo2(ull v) {
    float a, b; asm("mov.b64 {%0, %1}, %2;" : "=f"(a), "=f"(b) : "l"(v)); return a;
}
__device__ __forceinline__ float hi2(ull v) {
    float a, b; asm("mov.b64 {%0, %1}, %2;" : "=f"(a), "=f"(b) : "l"(v)); return b;
}
__device__ __forceinline__ ull ffma2(ull a, ull b, ull c) {
    ull d; asm("fma.rn.f32x2 %0, %1, %2, %3;" : "=l"(d) : "l"(a), "l"(b), "l"(c));
    return d;
}

// ---------------------------------------------------------------------------
// TF32 tensor-core GEMM, warp tile 64x64, double-buffered pair-smem.
// (unchanged from round 9 — committed WIN)
// ---------------------------------------------------------------------------
#define TBM 128
#define TBN 256
#define TBK 16
#define APAD 72
#define BPAD 264

__device__ __forceinline__ uint32_t f2tf(float f) {
    uint32_t u; asm("cvt.rna.tf32.f32 %0, %1;" : "=r"(u) : "f"(f)); return u;
}
__device__ __forceinline__ ull packtf(float lo, float hi) {
    return (ull)f2tf(lo) | ((ull)f2tf(hi) << 32);
}

__device__ __forceinline__ void mma_tf32(float c[4], uint32_t a0, uint32_t a1,
                                         uint32_t a2, uint32_t a3,
                                         uint32_t b0, uint32_t b1) {
    asm volatile(
        "mma.sync.aligned.m16n8k8.row.col.f32.tf32.tf32.f32 "
        "{%0,%1,%2,%3}, {%4,%5,%6,%7}, {%8,%9}, {%0,%1,%2,%3};"
        : "+f"(c[0]), "+f"(c[1]), "+f"(c[2]), "+f"(c[3])
        : "r"(a0), "r"(a1), "r"(a2), "r"(a3), "r"(b0), "r"(b1));
}

__global__ __launch_bounds__(256, 1)
void tf32gemm_kernel(const float* __restrict__ A,
                     const float* __restrict__ B0, const float* __restrict__ B1,
                     const float* __restrict__ B2,
                     float* __restrict__ C0, float* __restrict__ C1,
                     float* __restrict__ C2,
                     int M, int N, int K)
{
    const int z = blockIdx.z;
    const float* B = (z == 0) ? B0 : ((z == 1) ? B1 : B2);
    float*       C = (z == 0) ? C0 : ((z == 1) ? C1 : C2);

    __shared__ ull As2[2][TBK][APAD];
    __shared__ ull Bs2[2][8][BPAD];

    const int tid  = threadIdx.x;
    const int lane = tid & 31;
    const int wid  = tid >> 5;
    const int bx = blockIdx.x, by = blockIdx.y;

    const int g = lane >> 2;
    const int t = lane & 3;
    const int wm = (wid & 1) * 64;
    const int wn = (wid >> 1) * 64;
    const int rb0 = wm >> 4;

    const int pid = tid & 63;
    const int kh  = tid >> 6;
    const int am  = ((pid >> 3) << 4) + (pid & 7);
    const int rp  = tid >> 5;
    const int bk  = (rp & 3) + ((rp >> 2) << 3);
    const int bc  = (tid & 31) * 8;

    const float* Ap0 = A + (size_t)(by * TBM + am) * K + kh * 4;
    const float* Ap1 = Ap0 + (size_t)8 * K;
    const float* Bp  = B + (size_t)bk * N + bx * TBN + bc;

    float c[4][8][4];
#pragma unroll
    for (int i = 0; i < 4; i++)
#pragma unroll
        for (int j = 0; j < 8; j++)
#pragma unroll
            for (int e = 0; e < 4; e++) c[i][j][e] = 0.f;

    const int NT = K / TBK;

    float4 ra0 = *(const float4*)Ap0;
    float4 ra1 = *(const float4*)Ap1;
    float4 rb0_ = *(const float4*)Bp;
    float4 rb1_ = *(const float4*)(Bp + 4);
    float4 rb2_ = *(const float4*)(Bp + (size_t)4 * N);
    float4 rb3_ = *(const float4*)(Bp + (size_t)4 * N + 4);
    {
        As2[0][kh * 4 + 0][pid] = packtf(ra0.x, ra1.x);
        As2[0][kh * 4 + 1][pid] = packtf(ra0.y, ra1.y);
        As2[0][kh * 4 + 2][pid] = packtf(ra0.z, ra1.z);
        As2[0][kh * 4 + 3][pid] = packtf(ra0.w, ra1.w);
        Bs2[0][rp][bc + 0] = packtf(rb0_.x, rb2_.x);
        Bs2[0][rp][bc + 1] = packtf(rb0_.y, rb2_.y);
        Bs2[0][rp][bc + 2] = packtf(rb0_.z, rb2_.z);
        Bs2[0][rp][bc + 3] = packtf(rb0_.w, rb2_.w);
        Bs2[0][rp][bc + 4] = packtf(rb1_.x, rb3_.x);
        Bs2[0][rp][bc + 5] = packtf(rb1_.y, rb3_.y);
        Bs2[0][rp][bc + 6] = packtf(rb1_.z, rb3_.z);
        Bs2[0][rp][bc + 7] = packtf(rb1_.w, rb3_.w);
    }
    __syncthreads();

    for (int kt = 0; kt < NT; kt++) {
        const int cur = kt & 1;
        if (kt + 1 < NT) {
            ra0  = *(const float4*)(Ap0 + (kt + 1) * TBK);
            ra1  = *(const float4*)(Ap1 + (kt + 1) * TBK);
            const float* Bn = Bp + (size_t)(kt + 1) * TBK * N;
            rb0_ = *(const float4*)Bn;
            rb1_ = *(const float4*)(Bn + 4);
            rb2_ = *(const float4*)(Bn + (size_t)4 * N);
            rb3_ = *(const float4*)(Bn + (size_t)4 * N + 4);
        }

#pragma unroll
        for (int s = 0; s < 2; s++) {
            const int kA = s * 8 + t;
            const int sp = s * 4 + t;
            uint32_t af[4][4];
#pragma unroll
            for (int i = 0; i < 4; i++) {
                const int pi = (rb0 + i) * 8 + g;
                ull v0 = As2[cur][kA][pi];
                ull v1 = As2[cur][kA + 4][pi];
                af[i][0] = (uint32_t)v0; af[i][1] = (uint32_t)(v0 >> 32);
                af[i][2] = (uint32_t)v1; af[i][3] = (uint32_t)(v1 >> 32);
            }
            uint32_t bf[8][2];
#pragma unroll
            for (int j = 0; j < 8; j++) {
                ull v = Bs2[cur][sp][wn + j * 8 + g];
                bf[j][0] = (uint32_t)v; bf[j][1] = (uint32_t)(v >> 32);
            }
#pragma unroll
            for (int i = 0; i < 4; i++)
#pragma unroll
                for (int j = 0; j < 8; j++)
                    mma_tf32(c[i][j], af[i][0], af[i][1], af[i][2], af[i][3],
                             bf[j][0], bf[j][1]);
        }

        if (kt + 1 < NT) {
            const int nxt = cur ^ 1;
            As2[nxt][kh * 4 + 0][pid] = packtf(ra0.x, ra1.x);
            As2[nxt][kh * 4 + 1][pid] = packtf(ra0.y, ra1.y);
            As2[nxt][kh * 4 + 2][pid] = packtf(ra0.z, ra1.z);
            As2[nxt][kh * 4 + 3][pid] = packtf(ra0.w, ra1.w);
            Bs2[nxt][rp][bc + 0] = packtf(rb0_.x, rb2_.x);
            Bs2[nxt][rp][bc + 1] = packtf(rb0_.y, rb2_.y);
            Bs2[nxt][rp][bc + 2] = packtf(rb0_.z, rb2_.z);
            Bs2[nxt][rp][bc + 3] = packtf(rb0_.w, rb2_.w);
            Bs2[nxt][rp][bc + 4] = packtf(rb1_.x, rb3_.x);
            Bs2[nxt][rp][bc + 5] = packtf(rb1_.y, rb3_.y);
            Bs2[nxt][rp][bc + 6] = packtf(rb1_.z, rb3_.z);
            Bs2[nxt][rp][bc + 7] = packtf(rb1_.w, rb3_.w);
            __syncthreads();
        }
    }

#pragma unroll
    for (int i = 0; i < 4; i++) {
        const int row = by * TBM + wm + i * 16 + g;
#pragma unroll
        for (int j = 0; j < 8; j++) {
            const int col = bx * TBN + wn + j * 8 + 2 * t;
            *(float2*)&C[(size_t)row * N + col]       = make_float2(c[i][j][0], c[i][j][1]);
            *(float2*)&C[(size_t)(row + 8) * N + col] = make_float2(c[i][j][2], c[i][j][3]);
        }
    }
}

// ---------------------------------------------------------------------------
// Sparse chunked attention — 8 queries per warp (QB=64).
// Grid: (SEQ/64, HEADS, BATCH); 256 threads (8 warps).
// Same K/V smem reads per warp-chunk now serve 8 queries instead of 4
// (halves LDS per query). Per-query selection/softmax code identical to
// round 9 -> identical numerics. Dynamic smem (64.3 KB).
// ---------------------------------------------------------------------------
#define QB 64

// dynamic smem offsets (bytes)
#define SM_QST   0                        // float [64][64]   16384
#define SM_KT2   16384                    // ull   [64][32]   16384
#define SM_VS    32768                    // float [64][64]   16384
#define SM_PS    49152                    // float [8][64][8] 16384
#define SM_FAC   65536                    // float [64]         256
#define SM_TOTAL 65792

__device__ __forceinline__ void bcas(float& x, int i, int j, int k, bool desc) {
    float pv = __shfl_xor_sync(0xffffffffu, x, j);
    bool keep_min = (((i & j) == 0) == ((((i & k) == 0) ? 1 : 0) ^ (desc ? 1 : 0)));
    x = keep_min ? fminf(x, pv) : fmaxf(x, pv);
}

__global__ __launch_bounds__(256)
void attn_kernel(const float* __restrict__ q, const float* __restrict__ k,
                 const float* __restrict__ v, const float* __restrict__ imp,
                 const float* __restrict__ temps, float* __restrict__ out)
{
    extern __shared__ char smem[];
    float* q_sT  = (float*)(smem + SM_QST);   // [d][query]  (d*64 + q)
    ull*   kT2   = (ull*)  (smem + SM_KT2);   // [d][slot]   (d*32 + slot)
    float* v_s   = (float*)(smem + SM_VS);    // [j][d]      (j*64 + d)
    float* p_s   = (float*)(smem + SM_PS);    // [warp][key][query]
    float* fac_s = (float*)(smem + SM_FAC);   // [query]

    const int b  = blockIdx.z;
    const int h  = blockIdx.y;
    const int t0 = blockIdx.x * QB;
    const int tid  = threadIdx.x;
    const int lane = tid & 31;
    const int wid  = tid >> 5;

    // per-query factor: SCALE / clip(temp) * sigmoid((sigmoid(imp)-0.5)*10)
    if (tid < QB) {
        float tmp = temps[b * HEADS + h];
        tmp = fminf(fmaxf(tmp, 0.1f), 100.f);
        float is = imp[((size_t)b * SEQ + (t0 + tid)) * HEADS + h];
        float ip = 1.f / (1.f + expf(-is));
        float mw = 1.f / (1.f + expf(-((ip - 0.5f) * 10.f)));
        fac_s[tid] = (SCALEF / tmp) * mw;
    }

    // load 64 queries (transposed: q_sT[d][query])
    for (int i = tid; i < QB * DHEAD / 4; i += 256) {
        int qq = i >> 4;
        int dd = (i & 15) * 4;
        float4 qv = *(const float4*)&q[((size_t)b * SEQ + (t0 + qq)) * CDIM + h * DHEAD + dd];
        q_sT[(dd + 0) * QB + qq] = qv.x;
        q_sT[(dd + 1) * QB + qq] = qv.y;
        q_sT[(dd + 2) * QB + qq] = qv.z;
        q_sT[(dd + 3) * QB + qq] = qv.w;
    }

    ull acc2[8];
#pragma unroll
    for (int i = 0; i < 8; i++) acc2[i] = 0ull;
    const int d0 = lane * 2;
    const int qbase = wid * 8;

    for (int ck = 0; ck < NCHUNK; ck++) {
        __syncthreads();   // protects q_sT/fac_s first iter, tile reuse after
        const int kt0 = ck * CHUNK;

        // K: pair staging (thread loads rows slot, slot+32; writes 4 STS64)
        const float* kb = &k[((size_t)b * SEQ + kt0) * CDIM + h * DHEAD];
#pragma unroll
        for (int u = tid; u < 512; u += 256) {
            const int slot = u & 31;
            const int dq   = (u >> 5) * 4;
            const float* k0p = kb + (size_t)slot * CDIM + dq;
            float4 k0 = *(const float4*)k0p;
            float4 k1 = *(const float4*)(k0p + (size_t)32 * CDIM);
            kT2[(dq + 0) * 32 + slot] = pack2(k0.x, k1.x);
            kT2[(dq + 1) * 32 + slot] = pack2(k0.y, k1.y);
            kT2[(dq + 2) * 32 + slot] = pack2(k0.z, k1.z);
            kT2[(dq + 3) * 32 + slot] = pack2(k0.w, k1.w);
        }
        // V: float4 staging
#pragma unroll
        for (int i = tid; i < CHUNK * DHEAD / 4; i += 256) {
            int j  = i >> 4;
            int dd = (i & 15) * 4;
            *(float4*)&v_s[j * DHEAD + dd] =
                *(const float4*)&v[((size_t)b * SEQ + (kt0 + j)) * CDIM + h * DHEAD + dd];
        }
        __syncthreads();

        // scores: lane owns keys (lane, lane+32); 8 queries packed in 4 f32x2
        ull s0p[4] = {0,0,0,0}, s1p[4] = {0,0,0,0};
#pragma unroll 8
        for (int d = 0; d < DHEAD; d++) {
            ull kp = kT2[d * 32 + lane];
            const float* qrow = q_sT + d * QB + qbase;
            float4 qa = *(const float4*)qrow;        // broadcast LDS128
            float4 qb = *(const float4*)(qrow + 4);  // broadcast LDS128
            float k0v = lo2(kp), k1v = hi2(kp);
            ull k0d = pack2(k0v, k0v), k1d = pack2(k1v, k1v);
            ull q01 = pack2(qa.x, qa.y), q23 = pack2(qa.z, qa.w);
            ull q45 = pack2(qb.x, qb.y), q67 = pack2(qb.z, qb.w);
            s0p[0] = ffma2(q01, k0d, s0p[0]);
            s0p[1] = ffma2(q23, k0d, s0p[1]);
            s0p[2] = ffma2(q45, k0d, s0p[2]);
            s0p[3] = ffma2(q67, k0d, s0p[3]);
            s1p[0] = ffma2(q01, k1d, s1p[0]);
            s1p[1] = ffma2(q23, k1d, s1p[1]);
            s1p[2] = ffma2(q45, k1d, s1p[2]);
            s1p[3] = ffma2(q67, k1d, s1p[3]);
        }

        float s0[8] = { lo2(s0p[0]), hi2(s0p[0]), lo2(s0p[1]), hi2(s0p[1]),
                        lo2(s0p[2]), hi2(s0p[2]), lo2(s0p[3]), hi2(s0p[3]) };
        float s1[8] = { lo2(s1p[0]), hi2(s1p[0]), lo2(s1p[1]), hi2(s1p[1]),
                        lo2(s1p[2]), hi2(s1p[2]), lo2(s1p[3]), hi2(s1p[3]) };
        float p0[8], p1[8];

#pragma unroll
        for (int qi = 0; qi < 8; qi++) {
            float f  = fac_s[qbase + qi];
            float a0 = s0[qi] * f;
            float a1 = s1[qi] * f;

            // exact 32nd-largest of 64 via two-array bitonic split
            float hv = fmaxf(a0, a1);
            float lv = fminf(a0, a1);
#pragma unroll
            for (int kk = 2; kk <= 32; kk <<= 1) {
#pragma unroll
                for (int j = kk >> 1; j > 0; j >>= 1) {
                    bcas(hv, lane, j, kk, false);
                    bcas(lv, lane, j, kk, true);
                }
            }
            float D = fmaxf(hv, lv);
            float thr = D;
#pragma unroll
            for (int o = 16; o; o >>= 1)
                thr = fminf(thr, __shfl_xor_sync(0xffffffffu, thr, o));

            float m0 = (a0 >= thr) ? a0 : 0.f;
            float m1 = (a1 >= thr) ? a1 : 0.f;
            float mx = fmaxf(m0, m1);
#pragma unroll
            for (int o = 16; o; o >>= 1)
                mx = fmaxf(mx, __shfl_xor_sync(0xffffffffu, mx, o));
            float e0 = __expf(m0 - mx);
            float e1 = __expf(m1 - mx);
            float ds = e0 + e1;
#pragma unroll
            for (int o = 16; o; o >>= 1)
                ds += __shfl_xor_sync(0xffffffffu, ds, o);
            float inv = 1.f / ds;
            p0[qi] = e0 * inv;
            p1[qi] = e1 * inv;
        }

        // stage p to smem (warp-private), then PV with broadcast LDS128 p
        float* pw0 = p_s + ((size_t)wid * CHUNK + lane) * 8;
        float* pw1 = p_s + ((size_t)wid * CHUNK + lane + 32) * 8;
        *(float4*)(pw0 + 0) = make_float4(p0[0], p0[1], p0[2], p0[3]);
        *(float4*)(pw0 + 4) = make_float4(p0[4], p0[5], p0[6], p0[7]);
        *(float4*)(pw1 + 0) = make_float4(p1[0], p1[1], p1[2], p1[3]);
        *(float4*)(pw1 + 4) = make_float4(p1[4], p1[5], p1[6], p1[7]);
        __syncwarp();

#pragma unroll 8
        for (int j = 0; j < CHUNK; j++) {
            const float* pr = p_s + ((size_t)wid * CHUNK + j) * 8;
            float4 pa = *(const float4*)pr;         // broadcast
            float4 pb = *(const float4*)(pr + 4);   // broadcast
            float2 vv = *(const float2*)&v_s[j * DHEAD + d0];
            ull v2 = pack2(vv.x, vv.y);
            acc2[0] = ffma2(pack2(pa.x, pa.x), v2, acc2[0]);
            acc2[1] = ffma2(pack2(pa.y, pa.y), v2, acc2[1]);
            acc2[2] = ffma2(pack2(pa.z, pa.z), v2, acc2[2]);
            acc2[3] = ffma2(pack2(pa.w, pa.w), v2, acc2[3]);
            acc2[4] = ffma2(pack2(pb.x, pb.x), v2, acc2[4]);
            acc2[5] = ffma2(pack2(pb.y, pb.y), v2, acc2[5]);
            acc2[6] = ffma2(pack2(pb.z, pb.z), v2, acc2[6]);
            acc2[7] = ffma2(pack2(pb.w, pb.w), v2, acc2[7]);
        }
        __syncwarp();   // keep p_s stable until all lanes done reading
    }

    // write [B,T,C]; normalizer sum(p) == NCHUNK == 16 exactly
    const float invn = 1.f / 16.f;
#pragma unroll
    for (int qi = 0; qi < 8; qi++) {
        int ql = qbase + qi;
        float2 o2 = make_float2(lo2(acc2[qi]) * invn, hi2(acc2[qi]) * invn);
        *(float2*)&out[((size_t)b * SEQ + (t0 + ql)) * CDIM + h * DHEAD + d0] = o2;
    }
}

// ---------------------------------------------------------------------------
// Launch
// ---------------------------------------------------------------------------
extern "C" void kernel_launch(void* const* d_in, const int* in_sizes, int n_in,
                              void* d_out, int out_size)
{
    const float* x    = (const float*)d_in[0];
    const float* impS = (const float*)d_in[1];
    const float* temp = (const float*)d_in[2];
    const float* Wq   = (const float*)d_in[3];
    const float* Wk   = (const float*)d_in[4];
    const float* Wv   = (const float*)d_in[5];
    const float* Wo   = (const float*)d_in[6];
    float* outp = (float*)d_out;

    float *pq, *pk, *pv, *pa;
    cudaGetSymbolAddress((void**)&pq, g_q);
    cudaGetSymbolAddress((void**)&pk, g_k);
    cudaGetSymbolAddress((void**)&pv, g_v);
    cudaGetSymbolAddress((void**)&pa, g_attn);

    const int M = BATCH * SEQ;   // 4096
    const int N = CDIM;          // 1024
    const int K = CDIM;          // 1024

    // fused QKV projection on tensor cores (grid.z selects weight/output)
    dim3 g3(N / TBN, M / TBM, 3);
    tf32gemm_kernel<<<g3, 256>>>(x, Wq, Wk, Wv, pq, pk, pv, M, N, K);

    static int attn_smem_set = 0;
    if (!attn_smem_set) {
        cudaFuncSetAttribute(attn_kernel,
                             cudaFuncAttributeMaxDynamicSharedMemorySize, SM_TOTAL);
        attn_smem_set = 1;
    }
    dim3 agrid(SEQ / QB, HEADS, BATCH);
    attn_kernel<<<agrid, 256, SM_TOTAL>>>(pq, pk, pv, impS, temp, pa);

    dim3 g1(N / TBN, M / TBM, 1);
    tf32gemm_kernel<<<g1, 256>>>(pa, Wo, Wo, Wo, outp, outp, outp, M, N, K);
}

// round 15
// speedup vs baseline: 2.3865x; 1.0002x over previous
#include <cuda_runtime.h>
#include <math.h>
#include <stdint.h>

typedef unsigned long long ull;

// Problem constants
#define BATCH  4
#define SEQ    1024
#define CDIM   1024
#define HEADS  16
#define DHEAD  64
#define CHUNK  64
#define NCHUNK 16
#define TOPKN  32
#define SCALEF 0.125f   // 1/sqrt(64)

// Scratch (allocation-free rule: device globals)
__device__ float g_q[BATCH*SEQ*CDIM];
__device__ float g_k[BATCH*SEQ*CDIM];
__device__ float g_v[BATCH*SEQ*CDIM];
__device__ float g_attn[BATCH*SEQ*CDIM];

// ---------------- f32x2 packed helpers (Blackwell FFMA2 path) --------------
__device__ __forceinline__ ull pack2(float lo, float hi) {
    ull r; asm("mov.b64 %0, {%1, %2};" : "=l"(r) : "f"(lo), "f"(hi)); return r;
}
__device__ __forceinline__ float lo2(ull v) {
    float a, b; asm("mov.b64 {%0, %1}, %2;" : "=f"(a), "=f"(b) : "l"(v)); return a;
}
__device__ __forceinline__ float hi2(ull v) {
    float a, b; asm("mov.b64 {%0, %1}, %2;" : "=f"(a), "=f"(b) : "l"(v)); return b;
}
__device__ __forceinline__ ull ffma2(ull a, ull b, ull c) {
    ull d; asm("fma.rn.f32x2 %0, %1, %2, %3;" : "=l"(d) : "l"(a), "l"(b), "l"(c));
    return d;
}
// order-preserving float<->uint map (no NaNs in this data)
__device__ __forceinline__ unsigned f2u(float f) {
    unsigned x = __float_as_uint(f);
    return (x & 0x80000000u) ? ~x : (x | 0x80000000u);
}
__device__ __forceinline__ float u2f(unsigned u) {
    unsigned x = (u & 0x80000000u) ? (u & 0x7fffffffu) : ~u;
    return __uint_as_float(x);
}

// ---------------------------------------------------------------------------
// TF32 tensor-core GEMM, warp tile 64x64, double-buffered pair-smem.
// (unchanged from round 9 — committed WIN)
// ---------------------------------------------------------------------------
#define TBM 128
#define TBN 256
#define TBK 16
#define APAD 72
#define BPAD 264

__device__ __forceinline__ uint32_t f2tf(float f) {
    uint32_t u; asm("cvt.rna.tf32.f32 %0, %1;" : "=r"(u) : "f"(f)); return u;
}
__device__ __forceinline__ ull packtf(float lo, float hi) {
    return (ull)f2tf(lo) | ((ull)f2tf(hi) << 32);
}

__device__ __forceinline__ void mma_tf32(float c[4], uint32_t a0, uint32_t a1,
                                         uint32_t a2, uint32_t a3,
                                         uint32_t b0, uint32_t b1) {
    asm volatile(
        "mma.sync.aligned.m16n8k8.row.col.f32.tf32.tf32.f32 "
        "{%0,%1,%2,%3}, {%4,%5,%6,%7}, {%8,%9}, {%0,%1,%2,%3};"
        : "+f"(c[0]), "+f"(c[1]), "+f"(c[2]), "+f"(c[3])
        : "r"(a0), "r"(a1), "r"(a2), "r"(a3), "r"(b0), "r"(b1));
}

__global__ __launch_bounds__(256, 1)
void tf32gemm_kernel(const float* __restrict__ A,
                     const float* __restrict__ B0, const float* __restrict__ B1,
                     const float* __restrict__ B2,
                     float* __restrict__ C0, float* __restrict__ C1,
                     float* __restrict__ C2,
                     int M, int N, int K)
{
    const int z = blockIdx.z;
    const float* B = (z == 0) ? B0 : ((z == 1) ? B1 : B2);
    float*       C = (z == 0) ? C0 : ((z == 1) ? C1 : C2);

    __shared__ ull As2[2][TBK][APAD];
    __shared__ ull Bs2[2][8][BPAD];

    const int tid  = threadIdx.x;
    const int lane = tid & 31;
    const int wid  = tid >> 5;
    const int bx = blockIdx.x, by = blockIdx.y;

    const int g = lane >> 2;
    const int t = lane & 3;
    const int wm = (wid & 1) * 64;
    const int wn = (wid >> 1) * 64;
    const int rb0 = wm >> 4;

    const int pid = tid & 63;
    const int kh  = tid >> 6;
    const int am  = ((pid >> 3) << 4) + (pid & 7);
    const int rp  = tid >> 5;
    const int bk  = (rp & 3) + ((rp >> 2) << 3);
    const int bc  = (tid & 31) * 8;

    const float* Ap0 = A + (size_t)(by * TBM + am) * K + kh * 4;
    const float* Ap1 = Ap0 + (size_t)8 * K;
    const float* Bp  = B + (size_t)bk * N + bx * TBN + bc;

    float c[4][8][4];
#pragma unroll
    for (int i = 0; i < 4; i++)
#pragma unroll
        for (int j = 0; j < 8; j++)
#pragma unroll
            for (int e = 0; e < 4; e++) c[i][j][e] = 0.f;

    const int NT = K / TBK;

    float4 ra0 = *(const float4*)Ap0;
    float4 ra1 = *(const float4*)Ap1;
    float4 rb0_ = *(const float4*)Bp;
    float4 rb1_ = *(const float4*)(Bp + 4);
    float4 rb2_ = *(const float4*)(Bp + (size_t)4 * N);
    float4 rb3_ = *(const float4*)(Bp + (size_t)4 * N + 4);
    {
        As2[0][kh * 4 + 0][pid] = packtf(ra0.x, ra1.x);
        As2[0][kh * 4 + 1][pid] = packtf(ra0.y, ra1.y);
        As2[0][kh * 4 + 2][pid] = packtf(ra0.z, ra1.z);
        As2[0][kh * 4 + 3][pid] = packtf(ra0.w, ra1.w);
        Bs2[0][rp][bc + 0] = packtf(rb0_.x, rb2_.x);
        Bs2[0][rp][bc + 1] = packtf(rb0_.y, rb2_.y);
        Bs2[0][rp][bc + 2] = packtf(rb0_.z, rb2_.z);
        Bs2[0][rp][bc + 3] = packtf(rb0_.w, rb2_.w);
        Bs2[0][rp][bc + 4] = packtf(rb1_.x, rb3_.x);
        Bs2[0][rp][bc + 5] = packtf(rb1_.y, rb3_.y);
        Bs2[0][rp][bc + 6] = packtf(rb1_.z, rb3_.z);
        Bs2[0][rp][bc + 7] = packtf(rb1_.w, rb3_.w);
    }
    __syncthreads();

    for (int kt = 0; kt < NT; kt++) {
        const int cur = kt & 1;
        if (kt + 1 < NT) {
            ra0  = *(const float4*)(Ap0 + (kt + 1) * TBK);
            ra1  = *(const float4*)(Ap1 + (kt + 1) * TBK);
            const float* Bn = Bp + (size_t)(kt + 1) * TBK * N;
            rb0_ = *(const float4*)Bn;
            rb1_ = *(const float4*)(Bn + 4);
            rb2_ = *(const float4*)(Bn + (size_t)4 * N);
            rb3_ = *(const float4*)(Bn + (size_t)4 * N + 4);
        }

#pragma unroll
        for (int s = 0; s < 2; s++) {
            const int kA = s * 8 + t;
            const int sp = s * 4 + t;
            uint32_t af[4][4];
#pragma unroll
            for (int i = 0; i < 4; i++) {
                const int pi = (rb0 + i) * 8 + g;
                ull v0 = As2[cur][kA][pi];
                ull v1 = As2[cur][kA + 4][pi];
                af[i][0] = (uint32_t)v0; af[i][1] = (uint32_t)(v0 >> 32);
                af[i][2] = (uint32_t)v1; af[i][3] = (uint32_t)(v1 >> 32);
            }
            uint32_t bf[8][2];
#pragma unroll
            for (int j = 0; j < 8; j++) {
                ull v = Bs2[cur][sp][wn + j * 8 + g];
                bf[j][0] = (uint32_t)v; bf[j][1] = (uint32_t)(v >> 32);
            }
#pragma unroll
            for (int i = 0; i < 4; i++)
#pragma unroll
                for (int j = 0; j < 8; j++)
                    mma_tf32(c[i][j], af[i][0], af[i][1], af[i][2], af[i][3],
                             bf[j][0], bf[j][1]);
        }

        if (kt + 1 < NT) {
            const int nxt = cur ^ 1;
            As2[nxt][kh * 4 + 0][pid] = packtf(ra0.x, ra1.x);
            As2[nxt][kh * 4 + 1][pid] = packtf(ra0.y, ra1.y);
            As2[nxt][kh * 4 + 2][pid] = packtf(ra0.z, ra1.z);
            As2[nxt][kh * 4 + 3][pid] = packtf(ra0.w, ra1.w);
            Bs2[nxt][rp][bc + 0] = packtf(rb0_.x, rb2_.x);
            Bs2[nxt][rp][bc + 1] = packtf(rb0_.y, rb2_.y);
            Bs2[nxt][rp][bc + 2] = packtf(rb0_.z, rb2_.z);
            Bs2[nxt][rp][bc + 3] = packtf(rb0_.w, rb2_.w);
            Bs2[nxt][rp][bc + 4] = packtf(rb1_.x, rb3_.x);
            Bs2[nxt][rp][bc + 5] = packtf(rb1_.y, rb3_.y);
            Bs2[nxt][rp][bc + 6] = packtf(rb1_.z, rb3_.z);
            Bs2[nxt][rp][bc + 7] = packtf(rb1_.w, rb3_.w);
            __syncthreads();
        }
    }

#pragma unroll
    for (int i = 0; i < 4; i++) {
        const int row = by * TBM + wm + i * 16 + g;
#pragma unroll
        for (int j = 0; j < 8; j++) {
            const int col = bx * TBN + wn + j * 8 + 2 * t;
            *(float2*)&C[(size_t)row * N + col]       = make_float2(c[i][j][0], c[i][j][1]);
            *(float2*)&C[(size_t)(row + 8) * N + col] = make_float2(c[i][j][2], c[i][j][3]);
        }
    }
}

// ---------------------------------------------------------------------------
// Sparse chunked attention — 8 queries per warp (QB=64), prefetch-pipelined.
// Grid: (SEQ/64, HEADS, BATCH); 256 threads (8 warps).
// Chunk loop: sync -> STS(prefetched regs) -> LDG next chunk -> sync -> compute
// so global-load latency hides under compute. Selection micro-opts (mx via
// sorted lane 31; thr via REDUX min on monotone uint map) are bit-exact.
// ---------------------------------------------------------------------------
#define QB 64

// dynamic smem offsets (bytes)
#define SM_QST   0                        // float [64][64]   16384
#define SM_KT2   16384                    // ull   [64][32]   16384
#define SM_VS    32768                    // float [64][64]   16384
#define SM_PS    49152                    // float [8][64][8] 16384
#define SM_FAC   65536                    // float [64]         256
#define SM_TOTAL 65792

__device__ __forceinline__ void bcas(float& x, int i, int j, int k, bool desc) {
    float pv = __shfl_xor_sync(0xffffffffu, x, j);
    bool keep_min = (((i & j) == 0) == ((((i & k) == 0) ? 1 : 0) ^ (desc ? 1 : 0)));
    x = keep_min ? fminf(x, pv) : fmaxf(x, pv);
}

__global__ __launch_bounds__(256)
void attn_kernel(const float* __restrict__ q, const float* __restrict__ k,
                 const float* __restrict__ v, const float* __restrict__ imp,
                 const float* __restrict__ temps, float* __restrict__ out)
{
    extern __shared__ char smem[];
    float* q_sT  = (float*)(smem + SM_QST);   // [d][query]  (d*64 + q)
    ull*   kT2   = (ull*)  (smem + SM_KT2);   // [d][slot]   (d*32 + slot)
    float* v_s   = (float*)(smem + SM_VS);    // [j][d]      (j*64 + d)
    float* p_s   = (float*)(smem + SM_PS);    // [warp][key][query]
    float* fac_s = (float*)(smem + SM_FAC);   // [query]

    const int b  = blockIdx.z;
    const int h  = blockIdx.y;
    const int t0 = blockIdx.x * QB;
    const int tid  = threadIdx.x;
    const int lane = tid & 31;
    const int wid  = tid >> 5;

    // per-query factor: SCALE / clip(temp) * sigmoid((sigmoid(imp)-0.5)*10)
    if (tid < QB) {
        float tmp = temps[b * HEADS + h];
        tmp = fminf(fmaxf(tmp, 0.1f), 100.f);
        float is = imp[((size_t)b * SEQ + (t0 + tid)) * HEADS + h];
        float ip = 1.f / (1.f + expf(-is));
        float mw = 1.f / (1.f + expf(-((ip - 0.5f) * 10.f)));
        fac_s[tid] = (SCALEF / tmp) * mw;
    }

    // load 64 queries (transposed: q_sT[d][query])
    for (int i = tid; i < QB * DHEAD / 4; i += 256) {
        int qq = i >> 4;
        int dd = (i & 15) * 4;
        float4 qv = *(const float4*)&q[((size_t)b * SEQ + (t0 + qq)) * CDIM + h * DHEAD + dd];
        q_sT[(dd + 0) * QB + qq] = qv.x;
        q_sT[(dd + 1) * QB + qq] = qv.y;
        q_sT[(dd + 2) * QB + qq] = qv.z;
        q_sT[(dd + 3) * QB + qq] = qv.w;
    }

    ull acc2[8];
#pragma unroll
    for (int i = 0; i < 8; i++) acc2[i] = 0ull;
    const int d0 = lane * 2;
    const int qbase = wid * 8;

    // prefetch-address params
    // K: this thread stages rows (slot, slot+32) at d-quads dq0 and dq0+32
    const int slot = tid & 31;
    const int dq0  = (tid >> 5) * 4;            // 0..28
    // V: 4 units i = tid + n*256 -> row jv_n = (i>>4), cols dv = (i&15)*4
    const int dv   = (tid & 15) * 4;
    const int jv0  = tid >> 4;                  // 0..15 (then +16,+32,+48)
    const float* kb = &k[(size_t)b * SEQ * CDIM + h * DHEAD];
    const float* vb = &v[(size_t)b * SEQ * CDIM + h * DHEAD];

    float4 kr[4];   // K prefetch: (slot,dq0) (slot+32,dq0) (slot,dq0+32) (slot+32,dq0+32)
    float4 vr[4];   // V prefetch

    // prologue: load chunk 0
    {
        const float* kc = kb;   // chunk 0
        kr[0] = *(const float4*)(kc + (size_t)slot * CDIM + dq0);
        kr[1] = *(const float4*)(kc + (size_t)(slot + 32) * CDIM + dq0);
        kr[2] = *(const float4*)(kc + (size_t)slot * CDIM + dq0 + 32);
        kr[3] = *(const float4*)(kc + (size_t)(slot + 32) * CDIM + dq0 + 32);
        const float* vc = vb;
#pragma unroll
        for (int n = 0; n < 4; n++)
            vr[n] = *(const float4*)(vc + (size_t)(jv0 + n * 16) * CDIM + dv);
    }

    for (int ck = 0; ck < NCHUNK; ck++) {
        __syncthreads();   // prev compute done; also protects q_sT/fac_s iter 0

        // STS prefetched chunk
        kT2[(dq0 + 0) * 32 + slot] = pack2(kr[0].x, kr[1].x);
        kT2[(dq0 + 1) * 32 + slot] = pack2(kr[0].y, kr[1].y);
        kT2[(dq0 + 2) * 32 + slot] = pack2(kr[0].z, kr[1].z);
        kT2[(dq0 + 3) * 32 + slot] = pack2(kr[0].w, kr[1].w);
        kT2[(dq0 + 32) * 32 + slot] = pack2(kr[2].x, kr[3].x);
        kT2[(dq0 + 33) * 32 + slot] = pack2(kr[2].y, kr[3].y);
        kT2[(dq0 + 34) * 32 + slot] = pack2(kr[2].z, kr[3].z);
        kT2[(dq0 + 35) * 32 + slot] = pack2(kr[2].w, kr[3].w);
#pragma unroll
        for (int n = 0; n < 4; n++)
            *(float4*)&v_s[(jv0 + n * 16) * DHEAD + dv] = vr[n];

        // issue next chunk's LDGs (latency hides under this chunk's compute)
        if (ck + 1 < NCHUNK) {
            const float* kc = kb + (size_t)(ck + 1) * CHUNK * CDIM;
            kr[0] = *(const float4*)(kc + (size_t)slot * CDIM + dq0);
            kr[1] = *(const float4*)(kc + (size_t)(slot + 32) * CDIM + dq0);
            kr[2] = *(const float4*)(kc + (size_t)slot * CDIM + dq0 + 32);
            kr[3] = *(const float4*)(kc + (size_t)(slot + 32) * CDIM + dq0 + 32);
            const float* vc = vb + (size_t)(ck + 1) * CHUNK * CDIM;
#pragma unroll
            for (int n = 0; n < 4; n++)
                vr[n] = *(const float4*)(vc + (size_t)(jv0 + n * 16) * CDIM + dv);
        }
        __syncthreads();

        // scores: lane owns keys (lane, lane+32); 8 queries packed in 4 f32x2
        ull s0p[4] = {0,0,0,0}, s1p[4] = {0,0,0,0};
#pragma unroll 8
        for (int d = 0; d < DHEAD; d++) {
            ull kp = kT2[d * 32 + lane];
            const float* qrow = q_sT + d * QB + qbase;
            float4 qa = *(const float4*)qrow;        // broadcast LDS128
            float4 qb = *(const float4*)(qrow + 4);  // broadcast LDS128
            float k0v = lo2(kp), k1v = hi2(kp);
            ull k0d = pack2(k0v, k0v), k1d = pack2(k1v, k1v);
            ull q01 = pack2(qa.x, qa.y), q23 = pack2(qa.z, qa.w);
            ull q45 = pack2(qb.x, qb.y), q67 = pack2(qb.z, qb.w);
            s0p[0] = ffma2(q01, k0d, s0p[0]);
            s0p[1] = ffma2(q23, k0d, s0p[1]);
            s0p[2] = ffma2(q45, k0d, s0p[2]);
            s0p[3] = ffma2(q67, k0d, s0p[3]);
            s1p[0] = ffma2(q01, k1d, s1p[0]);
            s1p[1] = ffma2(q23, k1d, s1p[1]);
            s1p[2] = ffma2(q45, k1d, s1p[2]);
            s1p[3] = ffma2(q67, k1d, s1p[3]);
        }

        float s0[8] = { lo2(s0p[0]), hi2(s0p[0]), lo2(s0p[1]), hi2(s0p[1]),
                        lo2(s0p[2]), hi2(s0p[2]), lo2(s0p[3]), hi2(s0p[3]) };
        float s1[8] = { lo2(s1p[0]), hi2(s1p[0]), lo2(s1p[1]), hi2(s1p[1]),
                        lo2(s1p[2]), hi2(s1p[2]), lo2(s1p[3]), hi2(s1p[3]) };
        float p0[8], p1[8];

#pragma unroll
        for (int qi = 0; qi < 8; qi++) {
            float f  = fac_s[qbase + qi];
            float a0 = s0[qi] * f;
            float a1 = s1[qi] * f;

            // exact 32nd-largest of 64 via two-array bitonic split
            float hv = fmaxf(a0, a1);
            float lv = fminf(a0, a1);
#pragma unroll
            for (int kk = 2; kk <= 32; kk <<= 1) {
#pragma unroll
                for (int j = kk >> 1; j > 0; j >>= 1) {
                    bcas(hv, lane, j, kk, false);
                    bcas(lv, lane, j, kk, true);
                }
            }
            float D = fmaxf(hv, lv);
            // thr = min over lanes of D (exact, via monotone uint map + REDUX)
            float thr = u2f(__reduce_min_sync(0xffffffffu, f2u(D)));
            // global max = top of ascending-sorted hv (lane 31); with distinct
            // scores exactly 32 entries are zeroed, so masked max = max(gmax, 0)
            float gmax = __shfl_sync(0xffffffffu, hv, 31);
            float mx = fmaxf(gmax, 0.f);

            float m0 = (a0 >= thr) ? a0 : 0.f;
            float m1 = (a1 >= thr) ? a1 : 0.f;
            float e0 = __expf(m0 - mx);
            float e1 = __expf(m1 - mx);
            float ds = e0 + e1;
#pragma unroll
            for (int o = 16; o; o >>= 1)
                ds += __shfl_xor_sync(0xffffffffu, ds, o);
            float inv = 1.f / ds;
            p0[qi] = e0 * inv;
            p1[qi] = e1 * inv;
        }

        // stage p to smem (warp-private), then PV with broadcast LDS128 p
        float* pw0 = p_s + ((size_t)wid * CHUNK + lane) * 8;
        float* pw1 = p_s + ((size_t)wid * CHUNK + lane + 32) * 8;
        *(float4*)(pw0 + 0) = make_float4(p0[0], p0[1], p0[2], p0[3]);
        *(float4*)(pw0 + 4) = make_float4(p0[4], p0[5], p0[6], p0[7]);
        *(float4*)(pw1 + 0) = make_float4(p1[0], p1[1], p1[2], p1[3]);
        *(float4*)(pw1 + 4) = make_float4(p1[4], p1[5], p1[6], p1[7]);
        __syncwarp();

#pragma unroll 8
        for (int j = 0; j < CHUNK; j++) {
            const float* pr = p_s + ((size_t)wid * CHUNK + j) * 8;
            float4 pa = *(const float4*)pr;         // broadcast
            float4 pb = *(const float4*)(pr + 4);   // broadcast
            float2 vv = *(const float2*)&v_s[j * DHEAD + d0];
            ull v2 = pack2(vv.x, vv.y);
            acc2[0] = ffma2(pack2(pa.x, pa.x), v2, acc2[0]);
            acc2[1] = ffma2(pack2(pa.y, pa.y), v2, acc2[1]);
            acc2[2] = ffma2(pack2(pa.z, pa.z), v2, acc2[2]);
            acc2[3] = ffma2(pack2(pa.w, pa.w), v2, acc2[3]);
            acc2[4] = ffma2(pack2(pb.x, pb.x), v2, acc2[4]);
            acc2[5] = ffma2(pack2(pb.y, pb.y), v2, acc2[5]);
            acc2[6] = ffma2(pack2(pb.z, pb.z), v2, acc2[6]);
            acc2[7] = ffma2(pack2(pb.w, pb.w), v2, acc2[7]);
        }
        __syncwarp();   // keep p_s stable until all lanes done reading
    }

    // write [B,T,C]; normalizer sum(p) == NCHUNK == 16 exactly
    const float invn = 1.f / 16.f;
#pragma unroll
    for (int qi = 0; qi < 8; qi++) {
        int ql = qbase + qi;
        float2 o2 = make_float2(lo2(acc2[qi]) * invn, hi2(acc2[qi]) * invn);
        *(float2*)&out[((size_t)b * SEQ + (t0 + ql)) * CDIM + h * DHEAD + d0] = o2;
    }
}

// ---------------------------------------------------------------------------
// Launch
// ---------------------------------------------------------------------------
extern "C" void kernel_launch(void* const* d_in, const int* in_sizes, int n_in,
                              void* d_out, int out_size)
{
    const float* x    = (const float*)d_in[0];
    const float* impS = (const float*)d_in[1];
    const float* temp = (const float*)d_in[2];
    const float* Wq   = (const float*)d_in[3];
    const float* Wk   = (const float*)d_in[4];
    const float* Wv   = (const float*)d_in[5];
    const float* Wo   = (const float*)d_in[6];
    float* outp = (float*)d_out;

    float *pq, *pk, *pv, *pa;
    cudaGetSymbolAddress((void**)&pq, g_q);
    cudaGetSymbolAddress((void**)&pk, g_k);
    cudaGetSymbolAddress((void**)&pv, g_v);
    cudaGetSymbolAddress((void**)&pa, g_attn);

    const int M = BATCH * SEQ;   // 4096
    const int N = CDIM;          // 1024
    const int K = CDIM;          // 1024

    // fused QKV projection on tensor cores (grid.z selects weight/output)
    dim3 g3(N / TBN, M / TBM, 3);
    tf32gemm_kernel<<<g3, 256>>>(x, Wq, Wk, Wv, pq, pk, pv, M, N, K);

    static int attn_smem_set = 0;
    if (!attn_smem_set) {
        cudaFuncSetAttribute(attn_kernel,
                             cudaFuncAttributeMaxDynamicSharedMemorySize, SM_TOTAL);
        attn_smem_set = 1;
    }
    dim3 agrid(SEQ / QB, HEADS, BATCH);
    attn_kernel<<<agrid, 256, SM_TOTAL>>>(pq, pk, pv, impS, temp, pa);

    dim3 g1(N / TBN, M / TBM, 1);
    tf32gemm_kernel<<<g1, 256>>>(pa, Wo, Wo, Wo, outp, outp, outp, M, N, K);
}

// round 17
// speedup vs baseline: 2.5817x; 1.0818x over previous
#include <cuda_runtime.h>
#include <math.h>
#include <stdint.h>

typedef unsigned long long ull;

// Problem constants
#define BATCH  4
#define SEQ    1024
#define CDIM   1024
#define HEADS  16
#define DHEAD  64
#define CHUNK  64
#define NCHUNK 16
#define TOPKN  32
#define SCALEF 0.125f   // 1/sqrt(64)

// Scratch (allocation-free rule: device globals)
__device__ float g_q[BATCH*SEQ*CDIM];
__device__ float g_k[BATCH*SEQ*CDIM];
__device__ float g_v[BATCH*SEQ*CDIM];
__device__ float g_attn[BATCH*SEQ*CDIM];

// ---------------- f32x2 packed helpers (Blackwell FFMA2 path) --------------
__device__ __forceinline__ ull pack2(float lo, float hi) {
    ull r; asm("mov.b64 %0, {%1, %2};" : "=l"(r) : "f"(lo), "f"(hi)); return r;
}
__device__ __forceinline__ float lo2(ull v) {
    float a, b; asm("mov.b64 {%0, %1}, %2;" : "=f"(a), "=f"(b) : "l"(v)); return a;
}
__device__ __forceinline__ float hi2(ull v) {
    float a, b; asm("mov.b64 {%0, %1}, %2;" : "=f"(a), "=f"(b) : "l"(v)); return b;
}
__device__ __forceinline__ ull ffma2(ull a, ull b, ull c) {
    ull d; asm("fma.rn.f32x2 %0, %1, %2, %3;" : "=l"(d) : "l"(a), "l"(b), "l"(c));
    return d;
}
// order-preserving float<->uint map (no NaNs in this data)
__device__ __forceinline__ unsigned f2u(float f) {
    unsigned x = __float_as_uint(f);
    return (x & 0x80000000u) ? ~x : (x | 0x80000000u);
}
__device__ __forceinline__ float u2f(unsigned u) {
    unsigned x = (u & 0x80000000u) ? (u & 0x7fffffffu) : ~u;
    return __uint_as_float(x);
}

// ---------------------------------------------------------------------------
// TF32 tensor-core GEMM, warp tile 64x64, double-buffered pair-smem.
// (unchanged from round 9 — committed WIN)
// ---------------------------------------------------------------------------
#define TBM 128
#define TBN 256
#define TBK 16
#define APAD 72
#define BPAD 264

__device__ __forceinline__ uint32_t f2tf(float f) {
    uint32_t u; asm("cvt.rna.tf32.f32 %0, %1;" : "=r"(u) : "f"(f)); return u;
}
__device__ __forceinline__ ull packtf(float lo, float hi) {
    return (ull)f2tf(lo) | ((ull)f2tf(hi) << 32);
}

__device__ __forceinline__ void mma_tf32(float c[4], uint32_t a0, uint32_t a1,
                                         uint32_t a2, uint32_t a3,
                                         uint32_t b0, uint32_t b1) {
    asm volatile(
        "mma.sync.aligned.m16n8k8.row.col.f32.tf32.tf32.f32 "
        "{%0,%1,%2,%3}, {%4,%5,%6,%7}, {%8,%9}, {%0,%1,%2,%3};"
        : "+f"(c[0]), "+f"(c[1]), "+f"(c[2]), "+f"(c[3])
        : "r"(a0), "r"(a1), "r"(a2), "r"(a3), "r"(b0), "r"(b1));
}

__global__ __launch_bounds__(256, 1)
void tf32gemm_kernel(const float* __restrict__ A,
                     const float* __restrict__ B0, const float* __restrict__ B1,
                     const float* __restrict__ B2,
                     float* __restrict__ C0, float* __restrict__ C1,
                     float* __restrict__ C2,
                     int M, int N, int K)
{
    const int z = blockIdx.z;
    const float* B = (z == 0) ? B0 : ((z == 1) ? B1 : B2);
    float*       C = (z == 0) ? C0 : ((z == 1) ? C1 : C2);

    __shared__ ull As2[2][TBK][APAD];
    __shared__ ull Bs2[2][8][BPAD];

    const int tid  = threadIdx.x;
    const int lane = tid & 31;
    const int wid  = tid >> 5;
    const int bx = blockIdx.x, by = blockIdx.y;

    const int g = lane >> 2;
    const int t = lane & 3;
    const int wm = (wid & 1) * 64;
    const int wn = (wid >> 1) * 64;
    const int rb0 = wm >> 4;

    const int pid = tid & 63;
    const int kh  = tid >> 6;
    const int am  = ((pid >> 3) << 4) + (pid & 7);
    const int rp  = tid >> 5;
    const int bk  = (rp & 3) + ((rp >> 2) << 3);
    const int bc  = (tid & 31) * 8;

    const float* Ap0 = A + (size_t)(by * TBM + am) * K + kh * 4;
    const float* Ap1 = Ap0 + (size_t)8 * K;
    const float* Bp  = B + (size_t)bk * N + bx * TBN + bc;

    float c[4][8][4];
#pragma unroll
    for (int i = 0; i < 4; i++)
#pragma unroll
        for (int j = 0; j < 8; j++)
#pragma unroll
            for (int e = 0; e < 4; e++) c[i][j][e] = 0.f;

    const int NT = K / TBK;

    float4 ra0 = *(const float4*)Ap0;
    float4 ra1 = *(const float4*)Ap1;
    float4 rb0_ = *(const float4*)Bp;
    float4 rb1_ = *(const float4*)(Bp + 4);
    float4 rb2_ = *(const float4*)(Bp + (size_t)4 * N);
    float4 rb3_ = *(const float4*)(Bp + (size_t)4 * N + 4);
    {
        As2[0][kh * 4 + 0][pid] = packtf(ra0.x, ra1.x);
        As2[0][kh * 4 + 1][pid] = packtf(ra0.y, ra1.y);
        As2[0][kh * 4 + 2][pid] = packtf(ra0.z, ra1.z);
        As2[0][kh * 4 + 3][pid] = packtf(ra0.w, ra1.w);
        Bs2[0][rp][bc + 0] = packtf(rb0_.x, rb2_.x);
        Bs2[0][rp][bc + 1] = packtf(rb0_.y, rb2_.y);
        Bs2[0][rp][bc + 2] = packtf(rb0_.z, rb2_.z);
        Bs2[0][rp][bc + 3] = packtf(rb0_.w, rb2_.w);
        Bs2[0][rp][bc + 4] = packtf(rb1_.x, rb3_.x);
        Bs2[0][rp][bc + 5] = packtf(rb1_.y, rb3_.y);
        Bs2[0][rp][bc + 6] = packtf(rb1_.z, rb3_.z);
        Bs2[0][rp][bc + 7] = packtf(rb1_.w, rb3_.w);
    }
    __syncthreads();

    for (int kt = 0; kt < NT; kt++) {
        const int cur = kt & 1;
        if (kt + 1 < NT) {
            ra0  = *(const float4*)(Ap0 + (kt + 1) * TBK);
            ra1  = *(const float4*)(Ap1 + (kt + 1) * TBK);
            const float* Bn = Bp + (size_t)(kt + 1) * TBK * N;
            rb0_ = *(const float4*)Bn;
            rb1_ = *(const float4*)(Bn + 4);
            rb2_ = *(const float4*)(Bn + (size_t)4 * N);
            rb3_ = *(const float4*)(Bn + (size_t)4 * N + 4);
        }

#pragma unroll
        for (int s = 0; s < 2; s++) {
            const int kA = s * 8 + t;
            const int sp = s * 4 + t;
            uint32_t af[4][4];
#pragma unroll
            for (int i = 0; i < 4; i++) {
                const int pi = (rb0 + i) * 8 + g;
                ull v0 = As2[cur][kA][pi];
                ull v1 = As2[cur][kA + 4][pi];
                af[i][0] = (uint32_t)v0; af[i][1] = (uint32_t)(v0 >> 32);
                af[i][2] = (uint32_t)v1; af[i][3] = (uint32_t)(v1 >> 32);
            }
            uint32_t bf[8][2];
#pragma unroll
            for (int j = 0; j < 8; j++) {
                ull v = Bs2[cur][sp][wn + j * 8 + g];
                bf[j][0] = (uint32_t)v; bf[j][1] = (uint32_t)(v >> 32);
            }
#pragma unroll
            for (int i = 0; i < 4; i++)
#pragma unroll
                for (int j = 0; j < 8; j++)
                    mma_tf32(c[i][j], af[i][0], af[i][1], af[i][2], af[i][3],
                             bf[j][0], bf[j][1]);
        }

        if (kt + 1 < NT) {
            const int nxt = cur ^ 1;
            As2[nxt][kh * 4 + 0][pid] = packtf(ra0.x, ra1.x);
            As2[nxt][kh * 4 + 1][pid] = packtf(ra0.y, ra1.y);
            As2[nxt][kh * 4 + 2][pid] = packtf(ra0.z, ra1.z);
            As2[nxt][kh * 4 + 3][pid] = packtf(ra0.w, ra1.w);
            Bs2[nxt][rp][bc + 0] = packtf(rb0_.x, rb2_.x);
            Bs2[nxt][rp][bc + 1] = packtf(rb0_.y, rb2_.y);
            Bs2[nxt][rp][bc + 2] = packtf(rb0_.z, rb2_.z);
            Bs2[nxt][rp][bc + 3] = packtf(rb0_.w, rb2_.w);
            Bs2[nxt][rp][bc + 4] = packtf(rb1_.x, rb3_.x);
            Bs2[nxt][rp][bc + 5] = packtf(rb1_.y, rb3_.y);
            Bs2[nxt][rp][bc + 6] = packtf(rb1_.z, rb3_.z);
            Bs2[nxt][rp][bc + 7] = packtf(rb1_.w, rb3_.w);
            __syncthreads();
        }
    }

#pragma unroll
    for (int i = 0; i < 4; i++) {
        const int row = by * TBM + wm + i * 16 + g;
#pragma unroll
        for (int j = 0; j < 8; j++) {
            const int col = bx * TBN + wn + j * 8 + 2 * t;
            *(float2*)&C[(size_t)row * N + col]       = make_float2(c[i][j][0], c[i][j][1]);
            *(float2*)&C[(size_t)(row + 8) * N + col] = make_float2(c[i][j][2], c[i][j][3]);
        }
    }
}

// ---------------------------------------------------------------------------
// Sparse chunked attention — 8 queries/warp (QB=64), STAGE-MAJOR selection.
// Grid: (SEQ/64, HEADS, BATCH); 256 threads (8 warps).
// The bitonic-split selection and the softmax sums are looped stage-outer /
// query-inner so each warp has 16 independent SHFL chains in flight per stage
// (breaks the serial per-query latency chain). Ops identical per query ->
// bitwise-identical result to rounds 14/15.
// ---------------------------------------------------------------------------
#define QB 64

// dynamic smem offsets (bytes)
#define SM_QST   0                        // float [64][64]   16384
#define SM_KT2   16384                    // ull   [64][32]   16384
#define SM_VS    32768                    // float [64][64]   16384
#define SM_PS    49152                    // float [8][64][8] 16384
#define SM_FAC   65536                    // float [64]         256
#define SM_TOTAL 65792

__device__ __forceinline__ void bcas(float& x, int i, int j, int k, bool desc) {
    float pv = __shfl_xor_sync(0xffffffffu, x, j);
    bool keep_min = (((i & j) == 0) == ((((i & k) == 0) ? 1 : 0) ^ (desc ? 1 : 0)));
    x = keep_min ? fminf(x, pv) : fmaxf(x, pv);
}

__global__ __launch_bounds__(256)
void attn_kernel(const float* __restrict__ q, const float* __restrict__ k,
                 const float* __restrict__ v, const float* __restrict__ imp,
                 const float* __restrict__ temps, float* __restrict__ out)
{
    extern __shared__ char smem[];
    float* q_sT  = (float*)(smem + SM_QST);   // [d][query]  (d*64 + q)
    ull*   kT2   = (ull*)  (smem + SM_KT2);   // [d][slot]   (d*32 + slot)
    float* v_s   = (float*)(smem + SM_VS);    // [j][d]      (j*64 + d)
    float* p_s   = (float*)(smem + SM_PS);    // [warp][key][query]
    float* fac_s = (float*)(smem + SM_FAC);   // [query]

    const int b  = blockIdx.z;
    const int h  = blockIdx.y;
    const int t0 = blockIdx.x * QB;
    const int tid  = threadIdx.x;
    const int lane = tid & 31;
    const int wid  = tid >> 5;

    // per-query factor: SCALE / clip(temp) * sigmoid((sigmoid(imp)-0.5)*10)
    if (tid < QB) {
        float tmp = temps[b * HEADS + h];
        tmp = fminf(fmaxf(tmp, 0.1f), 100.f);
        float is = imp[((size_t)b * SEQ + (t0 + tid)) * HEADS + h];
        float ip = 1.f / (1.f + expf(-is));
        float mw = 1.f / (1.f + expf(-((ip - 0.5f) * 10.f)));
        fac_s[tid] = (SCALEF / tmp) * mw;
    }

    // load 64 queries (transposed: q_sT[d][query])
    for (int i = tid; i < QB * DHEAD / 4; i += 256) {
        int qq = i >> 4;
        int dd = (i & 15) * 4;
        float4 qv = *(const float4*)&q[((size_t)b * SEQ + (t0 + qq)) * CDIM + h * DHEAD + dd];
        q_sT[(dd + 0) * QB + qq] = qv.x;
        q_sT[(dd + 1) * QB + qq] = qv.y;
        q_sT[(dd + 2) * QB + qq] = qv.z;
        q_sT[(dd + 3) * QB + qq] = qv.w;
    }

    ull acc2[8];
#pragma unroll
    for (int i = 0; i < 8; i++) acc2[i] = 0ull;
    const int d0 = lane * 2;
    const int qbase = wid * 8;

    for (int ck = 0; ck < NCHUNK; ck++) {
        __syncthreads();   // protects q_sT/fac_s first iter, tile reuse after
        const int kt0 = ck * CHUNK;

        // K: pair staging (thread loads rows slot, slot+32; writes 4 STS64)
        const float* kb = &k[((size_t)b * SEQ + kt0) * CDIM + h * DHEAD];
#pragma unroll
        for (int u = tid; u < 512; u += 256) {
            const int slot = u & 31;
            const int dq   = (u >> 5) * 4;
            const float* k0p = kb + (size_t)slot * CDIM + dq;
            float4 k0 = *(const float4*)k0p;
            float4 k1 = *(const float4*)(k0p + (size_t)32 * CDIM);
            kT2[(dq + 0) * 32 + slot] = pack2(k0.x, k1.x);
            kT2[(dq + 1) * 32 + slot] = pack2(k0.y, k1.y);
            kT2[(dq + 2) * 32 + slot] = pack2(k0.z, k1.z);
            kT2[(dq + 3) * 32 + slot] = pack2(k0.w, k1.w);
        }
        // V: float4 staging
#pragma unroll
        for (int i = tid; i < CHUNK * DHEAD / 4; i += 256) {
            int j  = i >> 4;
            int dd = (i & 15) * 4;
            *(float4*)&v_s[j * DHEAD + dd] =
                *(const float4*)&v[((size_t)b * SEQ + (kt0 + j)) * CDIM + h * DHEAD + dd];
        }
        __syncthreads();

        // scores: lane owns keys (lane, lane+32); 8 queries packed in 4 f32x2
        ull s0p[4] = {0,0,0,0}, s1p[4] = {0,0,0,0};
#pragma unroll 8
        for (int d = 0; d < DHEAD; d++) {
            ull kp = kT2[d * 32 + lane];
            const float* qrow = q_sT + d * QB + qbase;
            float4 qa = *(const float4*)qrow;        // broadcast LDS128
            float4 qb = *(const float4*)(qrow + 4);  // broadcast LDS128
            float k0v = lo2(kp), k1v = hi2(kp);
            ull k0d = pack2(k0v, k0v), k1d = pack2(k1v, k1v);
            ull q01 = pack2(qa.x, qa.y), q23 = pack2(qa.z, qa.w);
            ull q45 = pack2(qb.x, qb.y), q67 = pack2(qb.z, qb.w);
            s0p[0] = ffma2(q01, k0d, s0p[0]);
            s0p[1] = ffma2(q23, k0d, s0p[1]);
            s0p[2] = ffma2(q45, k0d, s0p[2]);
            s0p[3] = ffma2(q67, k0d, s0p[3]);
            s1p[0] = ffma2(q01, k1d, s1p[0]);
            s1p[1] = ffma2(q23, k1d, s1p[1]);
            s1p[2] = ffma2(q45, k1d, s1p[2]);
            s1p[3] = ffma2(q67, k1d, s1p[3]);
        }

        // per-query scaled scores (a0 = key lane, a1 = key lane+32)
        float a0[8], a1[8], hv[8], lv[8];
        {
            float s0[8] = { lo2(s0p[0]), hi2(s0p[0]), lo2(s0p[1]), hi2(s0p[1]),
                            lo2(s0p[2]), hi2(s0p[2]), lo2(s0p[3]), hi2(s0p[3]) };
            float s1[8] = { lo2(s1p[0]), hi2(s1p[0]), lo2(s1p[1]), hi2(s1p[1]),
                            lo2(s1p[2]), hi2(s1p[2]), lo2(s1p[3]), hi2(s1p[3]) };
#pragma unroll
            for (int qi = 0; qi < 8; qi++) {
                float f = fac_s[qbase + qi];
                a0[qi] = s0[qi] * f;
                a1[qi] = s1[qi] * f;
                hv[qi] = fmaxf(a0[qi], a1[qi]);
                lv[qi] = fminf(a0[qi], a1[qi]);
            }
        }

        // exact 32nd-largest of 64 via two-array bitonic split, STAGE-MAJOR:
        // each stage issues 16 independent SHFL chains (8 hv asc + 8 lv desc)
#pragma unroll
        for (int kk = 2; kk <= 32; kk <<= 1) {
#pragma unroll
            for (int j = kk >> 1; j > 0; j >>= 1) {
#pragma unroll
                for (int qi = 0; qi < 8; qi++) {
                    bcas(hv[qi], lane, j, kk, false);
                    bcas(lv[qi], lane, j, kk, true);
                }
            }
        }

        // thr / masked exp (independent per query; short chains interleave)
        float e0[8], e1[8], ds[8];
#pragma unroll
        for (int qi = 0; qi < 8; qi++) {
            float D = fmaxf(hv[qi], lv[qi]);
            float thr = u2f(__reduce_min_sync(0xffffffffu, f2u(D)));
            float gmax = __shfl_sync(0xffffffffu, hv[qi], 31);
            float mx = fmaxf(gmax, 0.f);
            float m0 = (a0[qi] >= thr) ? a0[qi] : 0.f;
            float m1 = (a1[qi] >= thr) ? a1[qi] : 0.f;
            e0[qi] = __expf(m0 - mx);
            e1[qi] = __expf(m1 - mx);
            ds[qi] = e0[qi] + e1[qi];
        }
        // softmax denominator: stage-major tree (8 independent chains/stage)
#pragma unroll
        for (int o = 16; o; o >>= 1)
#pragma unroll
            for (int qi = 0; qi < 8; qi++)
                ds[qi] += __shfl_xor_sync(0xffffffffu, ds[qi], o);

        float p0[8], p1[8];
#pragma unroll
        for (int qi = 0; qi < 8; qi++) {
            float inv = 1.f / ds[qi];
            p0[qi] = e0[qi] * inv;
            p1[qi] = e1[qi] * inv;
        }

        // stage p to smem (warp-private), then PV with broadcast LDS128 p
        float* pw0 = p_s + ((size_t)wid * CHUNK + lane) * 8;
        float* pw1 = p_s + ((size_t)wid * CHUNK + lane + 32) * 8;
        *(float4*)(pw0 + 0) = make_float4(p0[0], p0[1], p0[2], p0[3]);
        *(float4*)(pw0 + 4) = make_float4(p0[4], p0[5], p0[6], p0[7]);
        *(float4*)(pw1 + 0) = make_float4(p1[0], p1[1], p1[2], p1[3]);
        *(float4*)(pw1 + 4) = make_float4(p1[4], p1[5], p1[6], p1[7]);
        __syncwarp();

#pragma unroll 8
        for (int j = 0; j < CHUNK; j++) {
            const float* pr = p_s + ((size_t)wid * CHUNK + j) * 8;
            float4 pa = *(const float4*)pr;         // broadcast
            float4 pb = *(const float4*)(pr + 4);   // broadcast
            float2 vv = *(const float2*)&v_s[j * DHEAD + d0];
            ull v2 = pack2(vv.x, vv.y);
            acc2[0] = ffma2(pack2(pa.x, pa.x), v2, acc2[0]);
            acc2[1] = ffma2(pack2(pa.y, pa.y), v2, acc2[1]);
            acc2[2] = ffma2(pack2(pa.z, pa.z), v2, acc2[2]);
            acc2[3] = ffma2(pack2(pa.w, pa.w), v2, acc2[3]);
            acc2[4] = ffma2(pack2(pb.x, pb.x), v2, acc2[4]);
            acc2[5] = ffma2(pack2(pb.y, pb.y), v2, acc2[5]);
            acc2[6] = ffma2(pack2(pb.z, pb.z), v2, acc2[6]);
            acc2[7] = ffma2(pack2(pb.w, pb.w), v2, acc2[7]);
        }
        __syncwarp();   // keep p_s stable until all lanes done reading
    }

    // write [B,T,C]; normalizer sum(p) == NCHUNK == 16 exactly
    const float invn = 1.f / 16.f;
#pragma unroll
    for (int qi = 0; qi < 8; qi++) {
        int ql = qbase + qi;
        float2 o2 = make_float2(lo2(acc2[qi]) * invn, hi2(acc2[qi]) * invn);
        *(float2*)&out[((size_t)b * SEQ + (t0 + ql)) * CDIM + h * DHEAD + d0] = o2;
    }
}

// ---------------------------------------------------------------------------
// Launch
// ---------------------------------------------------------------------------
extern "C" void kernel_launch(void* const* d_in, const int* in_sizes, int n_in,
                              void* d_out, int out_size)
{
    const float* x    = (const float*)d_in[0];
    const float* impS = (const float*)d_in[1];
    const float* temp = (const float*)d_in[2];
    const float* Wq   = (const float*)d_in[3];
    const float* Wk   = (const float*)d_in[4];
    const float* Wv   = (const float*)d_in[5];
    const float* Wo   = (const float*)d_in[6];
    float* outp = (float*)d_out;

    float *pq, *pk, *pv, *pa;
    cudaGetSymbolAddress((void**)&pq, g_q);
    cudaGetSymbolAddress((void**)&pk, g_k);
    cudaGetSymbolAddress((void**)&pv, g_v);
    cudaGetSymbolAddress((void**)&pa, g_attn);

    const int M = BATCH * SEQ;   // 4096
    const int N = CDIM;          // 1024
    const int K = CDIM;          // 1024

    // fused QKV projection on tensor cores (grid.z selects weight/output)
    dim3 g3(N / TBN, M / TBM, 3);
    tf32gemm_kernel<<<g3, 256>>>(x, Wq, Wk, Wv, pq, pk, pv, M, N, K);

    static int attn_smem_set = 0;
    if (!attn_smem_set) {
        cudaFuncSetAttribute(attn_kernel,
                             cudaFuncAttributeMaxDynamicSharedMemorySize, SM_TOTAL);
        attn_smem_set = 1;
    }
    dim3 agrid(SEQ / QB, HEADS, BATCH);
    attn_kernel<<<agrid, 256, SM_TOTAL>>>(pq, pk, pv, impS, temp, pa);

    dim3 g1(N / TBN, M / TBM, 1);
    tf32gemm_kernel<<<g1, 256>>>(pa, Wo, Wo, Wo, outp, outp, outp, M, N, K);
}